// round 12
// baseline (speedup 1.0000x reference)
#include <cuda_runtime.h>
#include <cuda_bf16.h>
#include <cstdint>
#include <math.h>

#define BB 2
#define SS 4096
#define DD 1024
#define HH 16
#define BLKSZ 64
#define NB 64
#define NGB 2
#define HDIM 64
#define MROWS (BB*SS)  // 8192

// ---------------------------------------------------------------------------
// Device scratch
// ---------------------------------------------------------------------------
__device__ int8_t g_xq_hi[(size_t)MROWS*DD];
__device__ int8_t g_xq_lo[(size_t)MROWS*DD];
__device__ float  g_xs[MROWS];
__device__ int8_t g_wq_hi[(size_t)3*DD*DD];   // [w][n][k]
__device__ int8_t g_wq_lo[(size_t)3*DD*DD];
__device__ float  g_ws[3*DD];
__device__ __nv_bfloat16 g_wu_hi[(size_t)DD*DD];   // Wu, [k][n]
__device__ __nv_bfloat16 g_wu_lo[(size_t)DD*DD];
__device__ __nv_bfloat16 g_c_hi[(size_t)MROWS*DD];
__device__ __nv_bfloat16 g_c_lo[(size_t)MROWS*DD];
__device__ __nv_bfloat16 g_qh[(size_t)BB*HH*SS*HDIM];
__device__ __nv_bfloat16 g_ql[(size_t)BB*HH*SS*HDIM];
__device__ __nv_bfloat16 g_kh[(size_t)BB*HH*SS*HDIM];
__device__ __nv_bfloat16 g_kl[(size_t)BB*HH*SS*HDIM];
__device__ __nv_bfloat16 g_vh[(size_t)BB*HH*SS*HDIM];
__device__ __nv_bfloat16 g_vl[(size_t)BB*HH*SS*HDIM];
__device__ float g_po[(size_t)512*4096];
__device__ float g_pm[512*64];
__device__ float g_pl[512*64];

// ---------------------------------------------------------------------------
// helpers
// ---------------------------------------------------------------------------
__device__ __forceinline__ uint32_t smem_u32(const void* p) {
    uint32_t a;
    asm("{ .reg .u64 t; cvta.to.shared.u64 t, %1; cvt.u32.u64 %0, t; }" : "=r"(a) : "l"(p));
    return a;
}
__device__ __forceinline__ void ldsm_x4(uint32_t* r, uint32_t addr) {
    asm volatile("ldmatrix.sync.aligned.m8n8.x4.shared.b16 {%0,%1,%2,%3}, [%4];"
        : "=r"(r[0]), "=r"(r[1]), "=r"(r[2]), "=r"(r[3]) : "r"(addr));
}
__device__ __forceinline__ void ldsm_x2(uint32_t* r, uint32_t addr) {
    asm volatile("ldmatrix.sync.aligned.m8n8.x2.shared.b16 {%0,%1}, [%2];"
        : "=r"(r[0]), "=r"(r[1]) : "r"(addr));
}
__device__ __forceinline__ void ldsm_x2_trans(uint32_t* r, uint32_t addr) {
    asm volatile("ldmatrix.sync.aligned.m8n8.x2.trans.shared.b16 {%0,%1}, [%2];"
        : "=r"(r[0]), "=r"(r[1]) : "r"(addr));
}
__device__ __forceinline__ void mma_bf16(float (&c)[4], const uint32_t* a,
                                         uint32_t b0, uint32_t b1) {
    asm volatile("mma.sync.aligned.m16n8k16.row.col.f32.bf16.bf16.f32 "
        "{%0,%1,%2,%3}, {%4,%5,%6,%7}, {%8,%9}, {%0,%1,%2,%3};"
        : "+f"(c[0]), "+f"(c[1]), "+f"(c[2]), "+f"(c[3])
        : "r"(a[0]), "r"(a[1]), "r"(a[2]), "r"(a[3]), "r"(b0), "r"(b1));
}
__device__ __forceinline__ void mma_s8(int (&c)[4], const uint32_t* a,
                                       uint32_t b0, uint32_t b1) {
    asm volatile("mma.sync.aligned.m16n8k32.row.col.s32.s8.s8.s32 "
        "{%0,%1,%2,%3}, {%4,%5,%6,%7}, {%8,%9}, {%0,%1,%2,%3};"
        : "+r"(c[0]), "+r"(c[1]), "+r"(c[2]), "+r"(c[3])
        : "r"(a[0]), "r"(a[1]), "r"(a[2]), "r"(a[3]), "r"(b0), "r"(b1));
}
__device__ __forceinline__ void cp_async16(uint32_t saddr, const void* gptr) {
    asm volatile("cp.async.cg.shared.global [%0], [%1], 16;" :: "r"(saddr), "l"(gptr));
}
#define CP_COMMIT asm volatile("cp.async.commit_group;")
#define CP_WAIT2  asm volatile("cp.async.wait_group 2;")
#define CP_WAIT1  asm volatile("cp.async.wait_group 1;")
#define CP_WAIT0  asm volatile("cp.async.wait_group 0;")

__device__ __forceinline__ uint32_t pack_hilo(float a, float b, uint32_t& lo_out) {
    __nv_bfloat162 h; h.x = __float2bfloat16(a); h.y = __float2bfloat16(b);
    __nv_bfloat162 l;
    l.x = __float2bfloat16(a - __bfloat162float(h.x));
    l.y = __float2bfloat16(b - __bfloat162float(h.y));
    lo_out = *(uint32_t*)&l;
    return *(uint32_t*)&h;
}
// int16 -> two signed int8 digits: q = hi*256 + lo
__device__ __forceinline__ void digit_split(int q, int8_t& hi, int8_t& lo) {
    int l = (int)(int8_t)(q & 0xFF);
    hi = (int8_t)((q - l) >> 8);
    lo = (int8_t)l;
}

// ---------------------------------------------------------------------------
// Quantize X per row: q = rn(x * 32512/rowmax), int16 -> int8 digits + scale
// one warp per row, 8 rows per block
// ---------------------------------------------------------------------------
__global__ __launch_bounds__(256) void quant_x_kernel(const float* __restrict__ X)
{
    const int row  = blockIdx.x * 8 + (threadIdx.x >> 5);
    const int lane = threadIdx.x & 31;
    const float* xr = X + (size_t)row * DD;

    float4 buf[8];
    float mx = 0.f;
#pragma unroll
    for (int j = 0; j < 8; j++) {
        buf[j] = ((const float4*)xr)[lane + j * 32];
        mx = fmaxf(mx, fmaxf(fmaxf(fabsf(buf[j].x), fabsf(buf[j].y)),
                             fmaxf(fabsf(buf[j].z), fabsf(buf[j].w))));
    }
#pragma unroll
    for (int o = 16; o; o >>= 1) mx = fmaxf(mx, __shfl_xor_sync(0xffffffffu, mx, o));
    float inv = (mx > 0.f) ? 32512.f / mx : 0.f;
    if (lane == 0) g_xs[row] = mx / 32512.f;

#pragma unroll
    for (int j = 0; j < 8; j++) {
        const float* f = &buf[j].x;
        char4 h4, l4;
        int8_t h, l;
        int q0 = __float2int_rn(f[0] * inv); digit_split(q0, h, l); h4.x = h; l4.x = l;
        int q1 = __float2int_rn(f[1] * inv); digit_split(q1, h, l); h4.y = h; l4.y = l;
        int q2 = __float2int_rn(f[2] * inv); digit_split(q2, h, l); h4.z = h; l4.z = l;
        int q3 = __float2int_rn(f[3] * inv); digit_split(q3, h, l); h4.w = h; l4.w = l;
        size_t idx = (size_t)row * DD + (lane + j * 32) * 4;
        *(char4*)(g_xq_hi + idx) = h4;
        *(char4*)(g_xq_lo + idx) = l4;
    }
}

// ---------------------------------------------------------------------------
// Per-column max of Wq/Wk/Wv -> scales. grid (32, 3), block 256.
// ---------------------------------------------------------------------------
__global__ __launch_bounds__(256) void wcolmax_kernel(
    const float* __restrict__ Wq, const float* __restrict__ Wk,
    const float* __restrict__ Wv)
{
    const float* W = (blockIdx.y == 0) ? Wq : (blockIdx.y == 1) ? Wk : Wv;
    const int n  = blockIdx.x * 32 + (threadIdx.x & 31);
    const int kg = threadIdx.x >> 5;
    float mx = 0.f;
    for (int k = kg; k < DD; k += 8) mx = fmaxf(mx, fabsf(W[(size_t)k * DD + n]));
    __shared__ float red[8][33];
    red[kg][threadIdx.x & 31] = mx;
    __syncthreads();
    if (kg == 0) {
#pragma unroll
        for (int j = 1; j < 8; j++) mx = fmaxf(mx, red[j][threadIdx.x & 31]);
        g_ws[blockIdx.y * DD + n] = mx / 32512.f;
    }
}

// ---------------------------------------------------------------------------
// Transpose + quantize Wq/Wk/Wv: W[k][n] -> int8 digit planes [n][k].
// grid (32, 32, 3), block (32, 8).
// ---------------------------------------------------------------------------
__global__ __launch_bounds__(256) void wquant_kernel(
    const float* __restrict__ Wq, const float* __restrict__ Wk,
    const float* __restrict__ Wv)
{
    __shared__ float tile[32][33];
    const int w = blockIdx.z;
    const float* W = (w == 0) ? Wq : (w == 1) ? Wk : Wv;
    const int n0 = blockIdx.x * 32;
    const int k0 = blockIdx.y * 32;
    const int tx = threadIdx.x;
    const int ty = threadIdx.y;

#pragma unroll
    for (int r = 0; r < 4; r++)
        tile[ty + 8 * r][tx] = W[(size_t)(k0 + ty + 8 * r) * DD + n0 + tx];
    __syncthreads();
#pragma unroll
    for (int r = 0; r < 4; r++) {
        const int n = n0 + ty + 8 * r;
        float s = g_ws[w * DD + n];
        float inv = (s > 0.f) ? 1.f / s : 0.f;
        int q = __float2int_rn(tile[tx][ty + 8 * r] * inv);
        int8_t h, l; digit_split(q, h, l);
        size_t idx = (size_t)w * DD * DD + (size_t)n * DD + k0 + tx;
        g_wq_hi[idx] = h;
        g_wq_lo[idx] = l;
    }
}

// ---------------------------------------------------------------------------
// bf16 split of Wu (keeps [k][n] layout for the out-GEMM)
// ---------------------------------------------------------------------------
__global__ __launch_bounds__(256) void wsplit_u_kernel(const float* __restrict__ Wu)
{
    size_t i = (size_t)blockIdx.x * 256 + threadIdx.x;
    float4 v = ((const float4*)Wu)[i];
    float vs[4] = {v.x, v.y, v.z, v.w};
    size_t base = i * 4;
#pragma unroll
    for (int j = 0; j < 4; j++) {
        __nv_bfloat16 hi = __float2bfloat16(vs[j]);
        float lo = vs[j] - __bfloat162float(hi);
        g_wu_hi[base + j] = hi;
        g_wu_lo[base + j] = __float2bfloat16(lo);
    }
}

// ---------------------------------------------------------------------------
// QKV int8 IMMA GEMM. CTA 128(M) x 64(N), K-chunk 64 (2 x k32), 3-stage
// cp.async. 8 warps: wm = wid&3 (32 rows), wn = wid>>2 (32 cols).
// Digit accumulation: C_int = 65536*HH + 256*(HL+LH); dequant by row/col scales.
// grid (16, 64, 3): blockIdx.z picks weight & output.
// ---------------------------------------------------------------------------
#define QSTR 80           // bytes per smem row (64 + 16 pad)
#define Q_AHI 0
#define Q_ALO 10240       // 128*80
#define Q_BHI 20480
#define Q_BLO 25600       // + 64*80
#define Q_STAGE 30720
#define QKV_SMEM_BYTES (3*Q_STAGE)   // 92160

__global__ __launch_bounds__(256, 2) void qkv_imma_kernel()
{
    extern __shared__ __align__(16) char qsm[];
    const uint32_t smem_base = smem_u32(qsm);

    const int t    = threadIdx.x;
    const int lane = t & 31;
    const int wid  = t >> 5;
    const int wm   = wid & 3;
    const int wn   = wid >> 2;
    const int w    = blockIdx.z;

    const int n0 = blockIdx.x * 64;
    const int m0 = blockIdx.y * 128;

    const int8_t* Bhi = g_wq_hi + (size_t)w * DD * DD;
    const int8_t* Blo = g_wq_lo + (size_t)w * DD * DD;

    int hh[2][4][4], cx[2][4][4];
#pragma unroll
    for (int mi = 0; mi < 2; mi++)
#pragma unroll
        for (int nj = 0; nj < 4; nj++)
#pragma unroll
            for (int e = 0; e < 4; e++) { hh[mi][nj][e] = 0; cx[mi][nj][e] = 0; }

#define QKV_PREFETCH(KC, SBUF) do {                                           \
    const int k0_ = (KC) * 64;                                                \
    const uint32_t sb_ = smem_base + (uint32_t)(SBUF) * Q_STAGE;              \
    _Pragma("unroll")                                                         \
    for (int j = 0; j < 6; j++) {                                             \
        int c = t + j * 256;                                                  \
        if (c < 1024) {                                                       \
            int pl = c >> 9, r = (c & 511) >> 2, seg = c & 3;                 \
            const int8_t* src = pl ? g_xq_lo : g_xq_hi;                       \
            uint32_t so = sb_ + (pl ? Q_ALO : Q_AHI) + r * QSTR + seg * 16;   \
            cp_async16(so, src + (size_t)(m0 + r) * DD + k0_ + seg * 16);     \
        } else {                                                              \
            int c2 = c - 1024;                                                \
            int pl = c2 >> 8, r = (c2 & 255) >> 2, seg = c2 & 3;              \
            const int8_t* src = pl ? Blo : Bhi;                               \
            uint32_t so = sb_ + (pl ? Q_BLO : Q_BHI) + r * QSTR + seg * 16;   \
            cp_async16(so, src + (size_t)(n0 + r) * DD + k0_ + seg * 16);     \
        }                                                                     \
    }                                                                         \
    CP_COMMIT; } while (0)

    QKV_PREFETCH(0, 0);
    QKV_PREFETCH(1, 1);

    int cs = 0, ps = 2;
    for (int kc = 0; kc < 16; kc++) {
        if (kc <= 13) { CP_WAIT1; } else { CP_WAIT0; }
        __syncthreads();
        if (kc + 2 < 16) {
            QKV_PREFETCH(kc + 2, ps);
            ps = (ps + 1 == 3) ? 0 : ps + 1;
        }

        const uint32_t sb = smem_base + (uint32_t)cs * Q_STAGE;
        cs = (cs + 1 == 3) ? 0 : cs + 1;
#pragma unroll
        for (int kk = 0; kk < 2; kk++) {
            uint32_t ah[2][4], al[2][4];
#pragma unroll
            for (int mi = 0; mi < 2; mi++) {
                uint32_t off = (uint32_t)((wm * 32 + mi * 16 + (lane & 15)) * QSTR
                               + kk * 32 + (lane >> 4) * 16);
                ldsm_x4(ah[mi], sb + Q_AHI + off);
                ldsm_x4(al[mi], sb + Q_ALO + off);
            }
            uint32_t bh[4][2], bl[4][2];
#pragma unroll
            for (int nj = 0; nj < 4; nj++) {
                uint32_t off = (uint32_t)((wn * 32 + nj * 8 + (lane & 7)) * QSTR
                               + kk * 32 + ((lane >> 3) & 1) * 16);
                ldsm_x2(bh[nj], sb + Q_BHI + off);
                ldsm_x2(bl[nj], sb + Q_BLO + off);
            }
#pragma unroll
            for (int mi = 0; mi < 2; mi++)
#pragma unroll
                for (int nj = 0; nj < 4; nj++) {
                    mma_s8(hh[mi][nj], ah[mi], bh[nj][0], bh[nj][1]);
                    mma_s8(cx[mi][nj], ah[mi], bl[nj][0], bl[nj][1]);
                    mma_s8(cx[mi][nj], al[mi], bh[nj][0], bh[nj][1]);
                }
        }
    }

    // Epilogue: dequant, pack bf16 hi/lo head-split q/k/v
    __nv_bfloat16* Oh = (w == 0) ? g_qh : (w == 1) ? g_kh : g_vh;
    __nv_bfloat16* Ol = (w == 0) ? g_ql : (w == 1) ? g_kl : g_vl;
#pragma unroll
    for (int mi = 0; mi < 2; mi++) {
        const int r0 = m0 + wm * 32 + mi * 16 + (lane >> 2);
#pragma unroll
        for (int nj = 0; nj < 4; nj++) {
            const int col = n0 + wn * 32 + nj * 8 + (lane & 3) * 2;
            const float sb0 = g_ws[w * DD + col];
            const float sb1 = g_ws[w * DD + col + 1];
            const int h  = col >> 6;
            const int dd = col & 63;
#pragma unroll
            for (int half = 0; half < 2; half++) {
                const int r = r0 + half * 8;
                const float sa = g_xs[r];
                float c0 = sa * sb0 * (65536.f * (float)hh[mi][nj][half*2+0]
                                       + 256.f * (float)cx[mi][nj][half*2+0]);
                float c1 = sa * sb1 * (65536.f * (float)hh[mi][nj][half*2+1]
                                       + 256.f * (float)cx[mi][nj][half*2+1]);
                int b_ = r >> 12, s = r & 4095;
                uint32_t lo, hi = pack_hilo(c0, c1, lo);
                size_t idx = (((size_t)(b_ * HH + h)) * SS + s) * HDIM + dd;
                *(uint32_t*)(Oh + idx) = hi;
                *(uint32_t*)(Ol + idx) = lo;
            }
        }
    }
}

// ---------------------------------------------------------------------------
// Output GEMM (proven R9 bf16 split, 3-stage): ctx @ Wu + bias -> out.
// ---------------------------------------------------------------------------
#define GK 32
#define SA2 40
#define SB2 136
#define SA_HI_B 0
#define SA_LO_B 10240
#define SB_HI_B 20480
#define SB_LO_B 29184
#define STAGE_B 37888
#define NSTAGE 3
#define GEMM_SMEM_BYTES (NSTAGE*STAGE_B)

__global__ __launch_bounds__(256, 2) void out_gemm_kernel(
    const float* __restrict__ bias, float* __restrict__ out_ptr)
{
    extern __shared__ __align__(16) char gsm[];
    const uint32_t smem_base = smem_u32(gsm);

    const int t    = threadIdx.x;
    const int lane = t & 31;
    const int wid  = t >> 5;
    const int wm   = wid & 3;
    const int wn   = wid >> 2;

    const int n0 = blockIdx.x * 128;
    const int m0 = blockIdx.y * 128;

    float acc[2][8][4];
#pragma unroll
    for (int mi = 0; mi < 2; mi++)
#pragma unroll
        for (int nj = 0; nj < 8; nj++)
#pragma unroll
            for (int e = 0; e < 4; e++) acc[mi][nj][e] = 0.f;

    const int lrow = lane & 15;
    const int lcol = (lane >> 4) * 8;

    const int arow0 = t >> 2,          aseg0 = (t & 3) * 8;
    const int arow1 = (t + 256) >> 2,  aseg1 = ((t + 256) & 3) * 8;
    const int brow0 = t >> 4,          bseg0 = (t & 15) * 8;
    const int brow1 = (t + 256) >> 4,  bseg1 = ((t + 256) & 15) * 8;

#define OGEMM_PREFETCH(KC, SBUF) do {                                       \
    const int k0_ = (KC) * GK;                                              \
    const uint32_t sb_ = smem_base + (uint32_t)(SBUF) * STAGE_B;            \
    {   size_t go = (size_t)(m0 + arow0) * DD + k0_ + aseg0;                \
        uint32_t so = sb_ + (uint32_t)(arow0 * SA2 + aseg0) * 2;            \
        cp_async16(so + SA_HI_B, g_c_hi + go);                              \
        cp_async16(so + SA_LO_B, g_c_lo + go); }                            \
    {   size_t go = (size_t)(m0 + arow1) * DD + k0_ + aseg1;                \
        uint32_t so = sb_ + (uint32_t)(arow1 * SA2 + aseg1) * 2;            \
        cp_async16(so + SA_HI_B, g_c_hi + go);                              \
        cp_async16(so + SA_LO_B, g_c_lo + go); }                            \
    {   size_t go = (size_t)(k0_ + brow0) * DD + n0 + bseg0;                \
        uint32_t so = sb_ + (uint32_t)(brow0 * SB2 + bseg0) * 2;            \
        cp_async16(so + SB_HI_B, g_wu_hi + go);                             \
        cp_async16(so + SB_LO_B, g_wu_lo + go); }                           \
    {   size_t go = (size_t)(k0_ + brow1) * DD + n0 + bseg1;                \
        uint32_t so = sb_ + (uint32_t)(brow1 * SB2 + bseg1) * 2;            \
        cp_async16(so + SB_HI_B, g_wu_hi + go);                             \
        cp_async16(so + SB_LO_B, g_wu_lo + go); }                           \
    CP_COMMIT; } while (0)

    OGEMM_PREFETCH(0, 0);
    OGEMM_PREFETCH(1, 1);

    int cs = 0, ps = 2;
    for (int kc = 0; kc < 32; kc++) {
        if (kc <= 29) { CP_WAIT1; } else { CP_WAIT0; }
        __syncthreads();
        if (kc + 2 < 32) {
            OGEMM_PREFETCH(kc + 2, ps);
            ps = (ps + 1 == NSTAGE) ? 0 : ps + 1;
        }

        const uint32_t sb = smem_base + (uint32_t)cs * STAGE_B;
        cs = (cs + 1 == NSTAGE) ? 0 : cs + 1;
#pragma unroll
        for (int kk = 0; kk < 2; kk++) {
            uint32_t ah[2][4], al[2][4];
#pragma unroll
            for (int mi = 0; mi < 2; mi++) {
                uint32_t off = (uint32_t)((wm * 32 + mi * 16 + lrow) * SA2 + kk * 16 + lcol) * 2;
                ldsm_x4(ah[mi], sb + SA_HI_B + off);
                ldsm_x4(al[mi], sb + SA_LO_B + off);
            }
            uint32_t bh[8][2], bl[8][2];
#pragma unroll
            for (int nj = 0; nj < 8; nj++) {
                uint32_t off = (uint32_t)((kk * 16 + lrow) * SB2 + wn * 64 + nj * 8) * 2;
                ldsm_x2_trans(bh[nj], sb + SB_HI_B + off);
                ldsm_x2_trans(bl[nj], sb + SB_LO_B + off);
            }
#pragma unroll
            for (int mi = 0; mi < 2; mi++)
#pragma unroll
                for (int nj = 0; nj < 8; nj++) {
                    mma_bf16(acc[mi][nj], ah[mi], bh[nj][0], bh[nj][1]);
                    mma_bf16(acc[mi][nj], ah[mi], bl[nj][0], bl[nj][1]);
                    mma_bf16(acc[mi][nj], al[mi], bh[nj][0], bh[nj][1]);
                }
        }
    }

#pragma unroll
    for (int mi = 0; mi < 2; mi++) {
        const int r0 = m0 + wm * 32 + mi * 16 + (lane >> 2);
#pragma unroll
        for (int nj = 0; nj < 8; nj++) {
            const int col = wn * 64 + nj * 8 + (lane & 3) * 2;
            float bv0 = bias[n0 + col], bv1 = bias[n0 + col + 1];
            float2 st0; st0.x = acc[mi][nj][0] + bv0; st0.y = acc[mi][nj][1] + bv1;
            float2 st1; st1.x = acc[mi][nj][2] + bv0; st1.y = acc[mi][nj][3] + bv1;
            *(float2*)(out_ptr + (size_t)r0 * DD + n0 + col) = st0;
            *(float2*)(out_ptr + (size_t)(r0 + 8) * DD + n0 + col) = st1;
        }
    }
}

// ---------------------------------------------------------------------------
// BigBird sparse attention (unchanged proven R9 state)
// ---------------------------------------------------------------------------
#define ATT_STRB 144
#define KSTAGE(s) ((s) * 18432)
#define T_VH 36864
#define T_VL 46080
#define T_PEN2 55296
#define T_PEN1 72704
#define ATTN_SMEM_BYTES 72976

__global__ __launch_bounds__(128, 3) void attn_kernel(
    const float* __restrict__ band_mask,
    const float* __restrict__ from_mask,
    const float* __restrict__ to_mask)
{
    extern __shared__ __align__(16) char smraw[];
    const uint32_t smem_base = smem_u32(smraw);
    const float* pen2f = (const float*)(smraw + T_PEN2);
    const float* pen1f = (const float*)(smraw + T_PEN1);

    const int bx = blockIdx.x;
    const int h  = blockIdx.y;
    const int b  = blockIdx.z;
    const int t  = threadIdx.x;
    const int lane = t & 31;
    const int wid  = t >> 5;

    const bool heavy = (bx >= 62);
    int qb, ch = 0;
    if (heavy) { int hx = bx - 62; qb = hx >> 3; ch = hx & 7; }
    else qb = bx + 2;

    const float rs  = 0.125f;
    const float pen = -10000.f;
    const size_t bh64 = ((size_t)(b * HH + h)) * SS * HDIM;

    {
        const __nv_bfloat16* qhp = g_qh + bh64 + (size_t)qb * BLKSZ * HDIM;
        const __nv_bfloat16* qlp = g_ql + bh64 + (size_t)qb * BLKSZ * HDIM;
        for (int i = t; i < 512; i += 128) {
            int row = i >> 3, seg = (i & 7) * 8;
            *(uint4*)(smraw + row * ATT_STRB + seg * 2)        = *(const uint4*)(qhp + row * HDIM + seg);
            *(uint4*)(smraw + 9216 + row * ATT_STRB + seg * 2) = *(const uint4*)(qlp + row * HDIM + seg);
        }
    }
    __syncthreads();

    uint32_t qfh[4][4], qfl[4][4];
    {
        const int lrow = lane & 15;
        const int lcol = (lane >> 4) * 8;
#pragma unroll
        for (int kk = 0; kk < 4; kk++) {
            uint32_t off = (uint32_t)((wid * 16 + lrow) * ATT_STRB + (kk * 16 + lcol) * 2);
            ldsm_x4(qfh[kk], smem_base + off);
            ldsm_x4(qfl[kk], smem_base + 9216 + off);
        }
    }
    __syncthreads();

    int nt;
    int kbs[5];
    bool is_band = false;
    if (heavy) {
        nt = 8;
    } else if (qb == NGB) {
        nt = 5; kbs[0]=0; kbs[1]=1; kbs[2]=2; kbs[3]=3; kbs[4]=4;
    } else if (qb == NB - 1) {
        nt = 5; kbs[0]=0; kbs[1]=1; kbs[2]=61; kbs[3]=62; kbs[4]=63;
    } else {
        nt = 5; kbs[0]=0; kbs[1]=1; kbs[2]=qb-1; kbs[3]=qb; kbs[4]=qb+1; is_band = true;
    }

#define KB_OF(IT) (heavy ? (ch * 8 + (IT)) : kbs[(IT)])

#define ISSUE_K(KB, STG) do {                                               \
    const __nv_bfloat16* khp_ = g_kh + bh64 + (size_t)(KB) * BLKSZ * HDIM;  \
    const __nv_bfloat16* klp_ = g_kl + bh64 + (size_t)(KB) * BLKSZ * HDIM;  \
    for (int i = t; i < 512; i += 128) {                                    \
        int row = i >> 3, seg = (i & 7) * 8;                                \
        uint32_t so = smem_base + KSTAGE(STG) + row * ATT_STRB + seg * 2;   \
        cp_async16(so,        khp_ + row * HDIM + seg);                     \
        cp_async16(so + 9216, klp_ + row * HDIM + seg);                     \
    }                                                                       \
    CP_COMMIT; } while (0)

#define ISSUE_VP(IT, KB, BANDT) do {                                        \
    const __nv_bfloat16* vhp_ = g_vh + bh64 + (size_t)(KB) * BLKSZ * HDIM;  \
    const __nv_bfloat16* vlp_ = g_vl + bh64 + (size_t)(KB) * BLKSZ * HDIM;  \
    for (int i = t; i < 512; i += 128) {                                    \
        int row = i >> 3, seg = (i & 7) * 8;                                \
        uint32_t so = smem_base + T_VH + row * ATT_STRB + seg * 2;          \
        cp_async16(so,        vhp_ + row * HDIM + seg);                     \
        cp_async16(so + 9216, vlp_ + row * HDIM + seg);                     \
    }                                                                       \
    if (BANDT) {                                                            \
        const float* bmb_ = band_mask                                       \
            + ((size_t)(b * 60 + (qb - 3)) * 64) * 192 + (size_t)((IT) - 2) * 64; \
        for (int i = t; i < 1024; i += 128) {                               \
            int row = i >> 4, c = i & 15;                                   \
            cp_async16(smem_base + T_PEN2 + row * 272 + c * 16,             \
                       bmb_ + row * 192 + c * 4);                           \
        }                                                                   \
    } else if (t < 16) {                                                    \
        cp_async16(smem_base + T_PEN1 + t * 16,                             \
                   to_mask + (size_t)b * SS + (KB) * BLKSZ + t * 4);        \
    }                                                                       \
    CP_COMMIT; } while (0)

    float m0 = -1e30f, m1 = -1e30f, l0 = 0.f, l1 = 0.f;
    float o[8][4];
#pragma unroll
    for (int nj = 0; nj < 8; nj++)
#pragma unroll
        for (int e = 0; e < 4; e++) o[nj][e] = 0.f;

    ISSUE_K(KB_OF(0), 0);

    for (int it = 0; it < nt; it++) {
        const int kb = KB_OF(it);
        const bool band_tile = (is_band && it >= 2);

        ISSUE_VP(it, kb, band_tile);
        if (it + 1 < nt) {
            ISSUE_K(KB_OF(it + 1), (it + 1) & 1);
            CP_WAIT2;
        } else {
            CP_WAIT1;
        }
        __syncthreads();

        const uint32_t kst = smem_base + KSTAGE(it & 1);
        float acc[8][4];
#pragma unroll
        for (int nj = 0; nj < 8; nj++)
#pragma unroll
            for (int e = 0; e < 4; e++) acc[nj][e] = 0.f;

#pragma unroll
        for (int nj = 0; nj < 8; nj++) {
            uint32_t kh8[8], kl8[8];
            uint32_t rbase = (uint32_t)((nj * 8 + (lane & 7)) * ATT_STRB + (lane >> 3) * 16);
            ldsm_x4(kh8,     kst + rbase);
            ldsm_x4(kh8 + 4, kst + rbase + 64);
            ldsm_x4(kl8,     kst + 9216 + rbase);
            ldsm_x4(kl8 + 4, kst + 9216 + rbase + 64);
#pragma unroll
            for (int kk = 0; kk < 4; kk++) {
                mma_bf16(acc[nj], qfh[kk], kh8[2*kk], kh8[2*kk+1]);
                mma_bf16(acc[nj], qfh[kk], kl8[2*kk], kl8[2*kk+1]);
                mma_bf16(acc[nj], qfl[kk], kh8[2*kk], kh8[2*kk+1]);
            }
        }

        if (it + 1 < nt) { CP_WAIT1; } else { CP_WAIT0; }
        __syncthreads();

        const int qr0 = wid * 16 + (lane >> 2);
#pragma unroll
        for (int nj = 0; nj < 8; nj++) {
#pragma unroll
            for (int e = 0; e < 4; e++) {
                int col = nj * 8 + (lane & 3) * 2 + (e & 1);
                float mv = band_tile
                    ? pen2f[(qr0 + (e >> 1) * 8) * 68 + col]
                    : pen1f[col];
                acc[nj][e] = acc[nj][e] * rs + (1.f - mv) * pen;
            }
        }

        float tm0 = -1e30f, tm1 = -1e30f;
#pragma unroll
        for (int nj = 0; nj < 8; nj++) {
            tm0 = fmaxf(tm0, fmaxf(acc[nj][0], acc[nj][1]));
            tm1 = fmaxf(tm1, fmaxf(acc[nj][2], acc[nj][3]));
        }
        tm0 = fmaxf(tm0, __shfl_xor_sync(0xffffffffu, tm0, 1));
        tm0 = fmaxf(tm0, __shfl_xor_sync(0xffffffffu, tm0, 2));
        tm1 = fmaxf(tm1, __shfl_xor_sync(0xffffffffu, tm1, 1));
        tm1 = fmaxf(tm1, __shfl_xor_sync(0xffffffffu, tm1, 2));

        float nm0 = fmaxf(m0, tm0), nm1 = fmaxf(m1, tm1);
        float c0 = __expf(m0 - nm0), c1 = __expf(m1 - nm1);
        float ts0 = 0.f, ts1 = 0.f;
#pragma unroll
        for (int nj = 0; nj < 8; nj++) {
            acc[nj][0] = __expf(acc[nj][0] - nm0);
            acc[nj][1] = __expf(acc[nj][1] - nm0);
            acc[nj][2] = __expf(acc[nj][2] - nm1);
            acc[nj][3] = __expf(acc[nj][3] - nm1);
            ts0 += acc[nj][0] + acc[nj][1];
            ts1 += acc[nj][2] + acc[nj][3];
        }
        ts0 += __shfl_xor_sync(0xffffffffu, ts0, 1);
        ts0 += __shfl_xor_sync(0xffffffffu, ts0, 2);
        ts1 += __shfl_xor_sync(0xffffffffu, ts1, 1);
        ts1 += __shfl_xor_sync(0xffffffffu, ts1, 2);
        l0 = l0 * c0 + ts0;  l1 = l1 * c1 + ts1;
        m0 = nm0;  m1 = nm1;
#pragma unroll
        for (int nj = 0; nj < 8; nj++) {
            o[nj][0] *= c0; o[nj][1] *= c0;
            o[nj][2] *= c1; o[nj][3] *= c1;
        }

        uint32_t phi[4][4], plo[4][4];
#pragma unroll
        for (int kk2 = 0; kk2 < 4; kk2++) {
            phi[kk2][0] = pack_hilo(acc[2*kk2][0],   acc[2*kk2][1],   plo[kk2][0]);
            phi[kk2][1] = pack_hilo(acc[2*kk2][2],   acc[2*kk2][3],   plo[kk2][1]);
            phi[kk2][2] = pack_hilo(acc[2*kk2+1][0], acc[2*kk2+1][1], plo[kk2][2]);
            phi[kk2][3] = pack_hilo(acc[2*kk2+1][2], acc[2*kk2+1][3], plo[kk2][3]);
        }

#pragma unroll
        for (int njd = 0; njd < 8; njd++) {
#pragma unroll
            for (int kk2 = 0; kk2 < 4; kk2++) {
                uint32_t vh[2], vl[2];
                uint32_t off = (uint32_t)((kk2 * 16 + (lane & 15)) * ATT_STRB + njd * 16);
                ldsm_x2_trans(vh, smem_base + T_VH + off);
                ldsm_x2_trans(vl, smem_base + T_VL + off);
                mma_bf16(o[njd], phi[kk2], vh[0], vh[1]);
                mma_bf16(o[njd], phi[kk2], vl[0], vl[1]);
                mma_bf16(o[njd], plo[kk2], vh[0], vh[1]);
            }
        }
        __syncthreads();
    }

    const int r0 = wid * 16 + (lane >> 2);
    if (!heavy) {
        const int s0 = qb * BLKSZ + r0;
        const int s1 = s0 + 8;
        float inv0 = from_mask[(size_t)b * SS + s0] / l0;
        float inv1 = from_mask[(size_t)b * SS + s1] / l1;
#pragma unroll
        for (int njd = 0; njd < 8; njd++) {
            const int col = njd * 8 + (lane & 3) * 2;
            {
                size_t idx = ((size_t)b * SS + s0) * DD + h * HDIM + col;
                uint32_t lo, hi = pack_hilo(o[njd][0] * inv0, o[njd][1] * inv0, lo);
                *(uint32_t*)(g_c_hi + idx) = hi;
                *(uint32_t*)(g_c_lo + idx) = lo;
            }
            {
                size_t idx = ((size_t)b * SS + s1) * DD + h * HDIM + col;
                uint32_t lo, hi = pack_hilo(o[njd][2] * inv1, o[njd][3] * inv1, lo);
                *(uint32_t*)(g_c_hi + idx) = hi;
                *(uint32_t*)(g_c_lo + idx) = lo;
            }
        }
    } else {
        const int cid = ((b * HH + h) * 2 + qb) * 8 + ch;
        float* pob = g_po + (size_t)cid * 4096;
#pragma unroll
        for (int njd = 0; njd < 8; njd++) {
            const int col = njd * 8 + (lane & 3) * 2;
            float2 s0v; s0v.x = o[njd][0]; s0v.y = o[njd][1];
            float2 s1v; s1v.x = o[njd][2]; s1v.y = o[njd][3];
            *(float2*)(pob + r0 * 64 + col) = s0v;
            *(float2*)(pob + (r0 + 8) * 64 + col) = s1v;
        }
        if ((lane & 3) == 0) {
            g_pm[cid * 64 + r0]     = m0;
            g_pm[cid * 64 + r0 + 8] = m1;
            g_pl[cid * 64 + r0]     = l0;
            g_pl[cid * 64 + r0 + 8] = l1;
        }
    }
}

// ---------------------------------------------------------------------------
// Combine split-KV partials
// ---------------------------------------------------------------------------
__global__ __launch_bounds__(128) void attn_combine(const float* __restrict__ from_mask)
{
    const int x  = blockIdx.x;
    const int qb = x & 1;
    const int h  = (x >> 1) & 15;
    const int b  = x >> 5;
    const int t  = threadIdx.x;
    const int r  = t >> 1;
    const int c0 = (t & 1) * 32;
    const int base8 = x * 8;

    float m[8], l[8], M = -1e30f;
#pragma unroll
    for (int i = 0; i < 8; i++) {
        m[i] = g_pm[(base8 + i) * 64 + r];
        l[i] = g_pl[(base8 + i) * 64 + r];
        M = fmaxf(M, m[i]);
    }
    float L = 0.f, sc[8];
#pragma unroll
    for (int i = 0; i < 8; i++) { sc[i] = __expf(m[i] - M); L += l[i] * sc[i]; }

    float acc[32];
#pragma unroll
    for (int c = 0; c < 32; c++) acc[c] = 0.f;
#pragma unroll
    for (int i = 0; i < 8; i++) {
        const float* p = g_po + (size_t)(base8 + i) * 4096 + r * 64 + c0;
        float s = sc[i];
#pragma unroll
        for (int c4 = 0; c4 < 8; c4++) {
            float4 v = *(const float4*)(p + c4 * 4);
            acc[c4*4+0] += s * v.x; acc[c4*4+1] += s * v.y;
            acc[c4*4+2] += s * v.z; acc[c4*4+3] += s * v.w;
        }
    }

    const int s_ = qb * BLKSZ + r;
    float inv = from_mask[(size_t)b * SS + s_] / L;
    size_t idx = ((size_t)b * SS + s_) * DD + h * HDIM + c0;
#pragma unroll
    for (int c = 0; c < 32; c += 2) {
        uint32_t lo, hi = pack_hilo(acc[c] * inv, acc[c+1] * inv, lo);
        *(uint32_t*)(g_c_hi + idx + c) = hi;
        *(uint32_t*)(g_c_lo + idx + c) = lo;
    }
}

// ---------------------------------------------------------------------------
extern "C" void kernel_launch(void* const* d_in, const int* in_sizes, int n_in,
                              void* d_out, int out_size)
{
    const float* tokens    = (const float*)d_in[0];
    const float* band_mask = (const float*)d_in[1];
    const float* from_mask = (const float*)d_in[2];
    const float* to_mask   = (const float*)d_in[3];
    const float* Wq        = (const float*)d_in[4];
    const float* Wk        = (const float*)d_in[5];
    const float* Wv        = (const float*)d_in[6];
    const float* Wu        = (const float*)d_in[7];
    const float* bu        = (const float*)d_in[8];
    float* out = (float*)d_out;

    cudaFuncSetAttribute(attn_kernel,
                         cudaFuncAttributeMaxDynamicSharedMemorySize, ATTN_SMEM_BYTES);
    cudaFuncSetAttribute(out_gemm_kernel,
                         cudaFuncAttributeMaxDynamicSharedMemorySize, GEMM_SMEM_BYTES);
    cudaFuncSetAttribute(qkv_imma_kernel,
                         cudaFuncAttributeMaxDynamicSharedMemorySize, QKV_SMEM_BYTES);

    // 0) Quantize X (int8 digits + row scales); quantize Wq/k/v; bf16-split Wu
    quant_x_kernel<<<MROWS / 8, 256>>>(tokens);
    wcolmax_kernel<<<dim3(32, 3), 256>>>(Wq, Wk, Wv);
    wquant_kernel<<<dim3(32, 32, 3), dim3(32, 8)>>>(Wq, Wk, Wv);
    wsplit_u_kernel<<<1024, 256>>>(Wu);

    // 1) QKV projections on int8 IMMA (digit-split)
    qkv_imma_kernel<<<dim3(16, 64, 3), 256, QKV_SMEM_BYTES>>>();

    // 2) Sparse attention (proven R9)
    attn_kernel<<<dim3(78, HH, BB), 128, ATTN_SMEM_BYTES>>>(band_mask, from_mask, to_mask);

    // 2b) Combine heavy partials
    attn_combine<<<64, 128>>>(from_mask);

    // 3) Output projection + bias (proven R9 bf16 split)
    out_gemm_kernel<<<dim3(8, 64), 256, GEMM_SMEM_BYTES>>>(bu, out);
}

// round 13
// speedup vs baseline: 1.8022x; 1.8022x over previous
#include <cuda_runtime.h>
#include <cuda_bf16.h>
#include <cstdint>
#include <math.h>

#define BB 2
#define SS 4096
#define DD 1024
#define HH 16
#define BLKSZ 64
#define NB 64          // S / BLK
#define NGB 2          // G / BLK
#define HDIM 64        // D / H
#define MROWS (BB*SS)  // 8192

// ---------------------------------------------------------------------------
// Device scratch (no allocation allowed)
// ---------------------------------------------------------------------------
__device__ __nv_bfloat16 g_x_hi[(size_t)MROWS*DD];
__device__ __nv_bfloat16 g_x_lo[(size_t)MROWS*DD];
__device__ __nv_bfloat16 g_c_hi[(size_t)MROWS*DD];
__device__ __nv_bfloat16 g_c_lo[(size_t)MROWS*DD];
__device__ __nv_bfloat16 g_w_hi[(size_t)4*DD*DD];   // [w][k][n] (native layout)
__device__ __nv_bfloat16 g_w_lo[(size_t)4*DD*DD];
// Q/K/V head-split bf16 hi/lo: [b,h,s,64]
__device__ __nv_bfloat16 g_qh[(size_t)BB*HH*SS*HDIM];
__device__ __nv_bfloat16 g_ql[(size_t)BB*HH*SS*HDIM];
__device__ __nv_bfloat16 g_kh[(size_t)BB*HH*SS*HDIM];
__device__ __nv_bfloat16 g_kl[(size_t)BB*HH*SS*HDIM];
__device__ __nv_bfloat16 g_vh[(size_t)BB*HH*SS*HDIM];
__device__ __nv_bfloat16 g_vl[(size_t)BB*HH*SS*HDIM];
// split-KV partials for heavy q-blocks
__device__ float g_po[(size_t)512*4096];
__device__ float g_pm[512*64];
__device__ float g_pl[512*64];

// ---------------------------------------------------------------------------
// mma.sync / ldmatrix / cp.async helpers (generic sm_80+ PTX)
// ---------------------------------------------------------------------------
__device__ __forceinline__ uint32_t smem_u32(const void* p) {
    uint32_t a;
    asm("{ .reg .u64 t; cvta.to.shared.u64 t, %1; cvt.u32.u64 %0, t; }" : "=r"(a) : "l"(p));
    return a;
}
__device__ __forceinline__ void ldsm_x4(uint32_t* r, uint32_t addr) {
    asm volatile("ldmatrix.sync.aligned.m8n8.x4.shared.b16 {%0,%1,%2,%3}, [%4];"
        : "=r"(r[0]), "=r"(r[1]), "=r"(r[2]), "=r"(r[3]) : "r"(addr));
}
__device__ __forceinline__ void ldsm_x2_trans(uint32_t* r, uint32_t addr) {
    asm volatile("ldmatrix.sync.aligned.m8n8.x2.trans.shared.b16 {%0,%1}, [%2];"
        : "=r"(r[0]), "=r"(r[1]) : "r"(addr));
}
__device__ __forceinline__ void mma_bf16(float (&c)[4], const uint32_t* a,
                                         uint32_t b0, uint32_t b1) {
    asm volatile("mma.sync.aligned.m16n8k16.row.col.f32.bf16.bf16.f32 "
        "{%0,%1,%2,%3}, {%4,%5,%6,%7}, {%8,%9}, {%0,%1,%2,%3};"
        : "+f"(c[0]), "+f"(c[1]), "+f"(c[2]), "+f"(c[3])
        : "r"(a[0]), "r"(a[1]), "r"(a[2]), "r"(a[3]), "r"(b0), "r"(b1));
}
__device__ __forceinline__ void cp_async16(uint32_t saddr, const void* gptr) {
    asm volatile("cp.async.cg.shared.global [%0], [%1], 16;" :: "r"(saddr), "l"(gptr));
}
#define CP_COMMIT asm volatile("cp.async.commit_group;")
#define CP_WAIT2  asm volatile("cp.async.wait_group 2;")
#define CP_WAIT1  asm volatile("cp.async.wait_group 1;")
#define CP_WAIT0  asm volatile("cp.async.wait_group 0;")

// pack two floats -> bf16x2 hi, bf16x2 lo (residual)
__device__ __forceinline__ uint32_t pack_hilo(float a, float b, uint32_t& lo_out) {
    __nv_bfloat162 h; h.x = __float2bfloat16(a); h.y = __float2bfloat16(b);
    __nv_bfloat162 l;
    l.x = __float2bfloat16(a - __bfloat162float(h.x));
    l.y = __float2bfloat16(b - __bfloat162float(h.y));
    lo_out = *(uint32_t*)&l;
    return *(uint32_t*)&h;
}

// ---------------------------------------------------------------------------
// Split tokens into bf16 hi/lo
// ---------------------------------------------------------------------------
__global__ __launch_bounds__(256) void split_x_kernel(const float* __restrict__ X)
{
    size_t i = (size_t)blockIdx.x * 256 + threadIdx.x;
    float4 v = ((const float4*)X)[i];
    float vs[4] = {v.x, v.y, v.z, v.w};
#pragma unroll
    for (int j = 0; j < 4; j++) {
        __nv_bfloat16 hi = __float2bfloat16(vs[j]);
        float lo = vs[j] - __bfloat162float(hi);
        g_x_hi[i * 4 + j] = hi;
        g_x_lo[i * 4 + j] = __float2bfloat16(lo);
    }
}

// ---------------------------------------------------------------------------
// Elementwise weight split (native [k][n] layout)
// ---------------------------------------------------------------------------
__global__ __launch_bounds__(256) void wsplit_kernel(
    const float* __restrict__ Wq, const float* __restrict__ Wk,
    const float* __restrict__ Wv, const float* __restrict__ Wu)
{
    const int w = blockIdx.y;
    const float* W = (w == 0) ? Wq : (w == 1) ? Wk : (w == 2) ? Wv : Wu;
    size_t i = (size_t)blockIdx.x * 256 + threadIdx.x;
    float4 v = ((const float4*)W)[i];
    float vs[4] = {v.x, v.y, v.z, v.w};
    size_t base = (size_t)w * DD * DD + i * 4;
#pragma unroll
    for (int j = 0; j < 4; j++) {
        __nv_bfloat16 hi = __float2bfloat16(vs[j]);
        float lo = vs[j] - __bfloat162float(hi);
        g_w_hi[base + j] = hi;
        g_w_lo[base + j] = __float2bfloat16(lo);
    }
}

// ---------------------------------------------------------------------------
// Split-bf16 HMMA GEMM, 3-stage cp.async pipeline (R9-proven mainloop).
// Epilogue for mode<3 now staged through smem for coalesced 16B stores.
// CTA 128x128, K-chunk 32. mode 0/1/2: bf16 hi/lo q/k/v; mode 3: fp32 + bias.
// ---------------------------------------------------------------------------
#define GK 32
#define SA2 40            // A stride (b16): 32 + 8 pad
#define SB2 136           // B stride (b16)
#define SA_HI_B 0
#define SA_LO_B 10240     // 128*40*2
#define SB_HI_B 20480
#define SB_LO_B 29184
#define STAGE_B 37888
#define NSTAGE 3
#define GEMM_SMEM_BYTES (NSTAGE*STAGE_B)
// epilogue staging overlays the pipeline buffers (after a barrier):
#define EP_STR 136                 // b16 stride for the 128x128 staging tile
#define EP_HI 0
#define EP_LO (128*EP_STR*2)       // 34816 bytes

__global__ __launch_bounds__(256, 2) void gemm_hmma_kernel(
    int mode_base, const float* __restrict__ bias, float* __restrict__ out_ptr)
{
    extern __shared__ __align__(16) char gsm[];
    const uint32_t smem_base = smem_u32(gsm);

    const int t    = threadIdx.x;
    const int lane = t & 31;
    const int wid  = t >> 5;
    const int wm   = wid & 3;
    const int wn   = wid >> 2;
    const int mode = mode_base + blockIdx.z;

    const int n0 = blockIdx.x * 128;
    const int m0 = blockIdx.y * 128;

    const __nv_bfloat16* Ahi = (mode < 3) ? g_x_hi : g_c_hi;
    const __nv_bfloat16* Alo = (mode < 3) ? g_x_lo : g_c_lo;
    const __nv_bfloat16* Bhi = g_w_hi + (size_t)mode * DD * DD;
    const __nv_bfloat16* Blo = g_w_lo + (size_t)mode * DD * DD;

    float acc[2][8][4];
#pragma unroll
    for (int mi = 0; mi < 2; mi++)
#pragma unroll
        for (int nj = 0; nj < 8; nj++)
#pragma unroll
            for (int e = 0; e < 4; e++) acc[mi][nj][e] = 0.f;

    const int lrow = lane & 15;
    const int lcol = (lane >> 4) * 8;

    const int arow0 = t >> 2,          aseg0 = (t & 3) * 8;
    const int arow1 = (t + 256) >> 2,  aseg1 = ((t + 256) & 3) * 8;
    const int brow0 = t >> 4,          bseg0 = (t & 15) * 8;
    const int brow1 = (t + 256) >> 4,  bseg1 = ((t + 256) & 15) * 8;

#define GEMM_PREFETCH(KC, SBUF) do {                                        \
    const int k0_ = (KC) * GK;                                              \
    const uint32_t sb_ = smem_base + (uint32_t)(SBUF) * STAGE_B;            \
    {   size_t go = (size_t)(m0 + arow0) * DD + k0_ + aseg0;                \
        uint32_t so = sb_ + (uint32_t)(arow0 * SA2 + aseg0) * 2;            \
        cp_async16(so + SA_HI_B, Ahi + go);                                 \
        cp_async16(so + SA_LO_B, Alo + go); }                               \
    {   size_t go = (size_t)(m0 + arow1) * DD + k0_ + aseg1;                \
        uint32_t so = sb_ + (uint32_t)(arow1 * SA2 + aseg1) * 2;            \
        cp_async16(so + SA_HI_B, Ahi + go);                                 \
        cp_async16(so + SA_LO_B, Alo + go); }                               \
    {   size_t go = (size_t)(k0_ + brow0) * DD + n0 + bseg0;                \
        uint32_t so = sb_ + (uint32_t)(brow0 * SB2 + bseg0) * 2;            \
        cp_async16(so + SB_HI_B, Bhi + go);                                 \
        cp_async16(so + SB_LO_B, Blo + go); }                               \
    {   size_t go = (size_t)(k0_ + brow1) * DD + n0 + bseg1;                \
        uint32_t so = sb_ + (uint32_t)(brow1 * SB2 + bseg1) * 2;            \
        cp_async16(so + SB_HI_B, Bhi + go);                                 \
        cp_async16(so + SB_LO_B, Blo + go); }                               \
    CP_COMMIT; } while (0)

    GEMM_PREFETCH(0, 0);
    GEMM_PREFETCH(1, 1);

    int cs = 0;          // compute buffer index for kc
    int ps = 2;          // prefetch buffer index for kc+2
    for (int kc = 0; kc < 32; kc++) {
        if (kc <= 29) { CP_WAIT1; } else { CP_WAIT0; }
        __syncthreads();
        if (kc + 2 < 32) {
            GEMM_PREFETCH(kc + 2, ps);
            ps = (ps + 1 == NSTAGE) ? 0 : ps + 1;
        }

        const uint32_t sb = smem_base + (uint32_t)cs * STAGE_B;
        cs = (cs + 1 == NSTAGE) ? 0 : cs + 1;
#pragma unroll
        for (int kk = 0; kk < 2; kk++) {
            uint32_t ah[2][4], al[2][4];
#pragma unroll
            for (int mi = 0; mi < 2; mi++) {
                uint32_t off = (uint32_t)((wm * 32 + mi * 16 + lrow) * SA2 + kk * 16 + lcol) * 2;
                ldsm_x4(ah[mi], sb + SA_HI_B + off);
                ldsm_x4(al[mi], sb + SA_LO_B + off);
            }
            uint32_t bh[8][2], bl[8][2];
#pragma unroll
            for (int nj = 0; nj < 8; nj++) {
                uint32_t off = (uint32_t)((kk * 16 + lrow) * SB2 + wn * 64 + nj * 8) * 2;
                ldsm_x2_trans(bh[nj], sb + SB_HI_B + off);
                ldsm_x2_trans(bl[nj], sb + SB_LO_B + off);
            }
#pragma unroll
            for (int mi = 0; mi < 2; mi++)
#pragma unroll
                for (int nj = 0; nj < 8; nj++) {
                    mma_bf16(acc[mi][nj], ah[mi], bh[nj][0], bh[nj][1]);
                    mma_bf16(acc[mi][nj], ah[mi], bl[nj][0], bl[nj][1]);
                    mma_bf16(acc[mi][nj], al[mi], bh[nj][0], bh[nj][1]);
                }
        }
    }

    if (mode < 3) {
        // ---- staged epilogue: pack to smem, then coalesced 16B stores ----
        __syncthreads();   // all warps done reading pipeline buffers
#pragma unroll
        for (int mi = 0; mi < 2; mi++) {
            const int rl0 = wm * 32 + mi * 16 + (lane >> 2);
#pragma unroll
            for (int nj = 0; nj < 8; nj++) {
                const int cl = wn * 64 + nj * 8 + (lane & 3) * 2;
#pragma unroll
                for (int half = 0; half < 2; half++) {
                    const int rl = rl0 + half * 8;
                    uint32_t lo, hi = pack_hilo(acc[mi][nj][half * 2 + 0],
                                                acc[mi][nj][half * 2 + 1], lo);
                    uint32_t off = (uint32_t)(rl * EP_STR + cl) * 2;
                    *(uint32_t*)(gsm + EP_HI + off) = hi;
                    *(uint32_t*)(gsm + EP_LO + off) = lo;
                }
            }
        }
        __syncthreads();

        __nv_bfloat16* Oh = (mode == 0) ? g_qh : (mode == 1) ? g_kh : g_vh;
        __nv_bfloat16* Ol = (mode == 0) ? g_ql : (mode == 1) ? g_kl : g_vl;
        // 128 rows x 16 segs of 16B (8 b16); consecutive t -> contiguous global
        for (int i = t; i < 2048; i += 256) {
            const int row = i >> 4;
            const int col = (i & 15) * 8;          // b16 col 0..120
            const int r   = m0 + row;
            const int b_  = r >> 12, s = r & 4095;
            const int h   = (n0 + col) >> 6;
            const int dd  = col & 63;
            size_t gidx = (((size_t)(b_ * HH + h)) * SS + s) * HDIM + dd;
            uint32_t soff = (uint32_t)(row * EP_STR + col) * 2;
            *(uint4*)(Oh + gidx) = *(const uint4*)(gsm + EP_HI + soff);
            *(uint4*)(Ol + gidx) = *(const uint4*)(gsm + EP_LO + soff);
        }
    } else {
        // ---- direct epilogue (fp32 out + bias), already 32B-chunk coalesced ----
#pragma unroll
        for (int mi = 0; mi < 2; mi++) {
            const int r0 = m0 + wm * 32 + mi * 16 + (lane >> 2);
#pragma unroll
            for (int nj = 0; nj < 8; nj++) {
                const int col = wn * 64 + nj * 8 + (lane & 3) * 2;
                float bv0 = bias[n0 + col], bv1 = bias[n0 + col + 1];
                float2 st0; st0.x = acc[mi][nj][0] + bv0; st0.y = acc[mi][nj][1] + bv1;
                float2 st1; st1.x = acc[mi][nj][2] + bv0; st1.y = acc[mi][nj][3] + bv1;
                *(float2*)(out_ptr + (size_t)r0 * DD + n0 + col) = st0;
                *(float2*)(out_ptr + (size_t)(r0 + 8) * DD + n0 + col) = st1;
            }
        }
    }
}

// ---------------------------------------------------------------------------
// BigBird sparse attention on HMMA, split-KV heavy blocks, cp.async pipelined
// (unchanged R9-proven state).
// ---------------------------------------------------------------------------
#define ATT_STRB 144                  // 72 b16 row stride, in bytes
#define KSTAGE(s) ((s) * 18432)       // per stage: KH +0, KL +9216
#define T_VH 36864
#define T_VL 46080
#define T_PEN2 55296                  // raw band_mask floats, 64 x 68 (stride 272B)
#define T_PEN1 72704                  // raw to_mask slice, 64 floats
#define ATTN_SMEM_BYTES 72976

__global__ __launch_bounds__(128, 3) void attn_kernel(
    const float* __restrict__ band_mask,
    const float* __restrict__ from_mask,
    const float* __restrict__ to_mask)
{
    extern __shared__ __align__(16) char smraw[];
    const uint32_t smem_base = smem_u32(smraw);
    const float* pen2f = (const float*)(smraw + T_PEN2);
    const float* pen1f = (const float*)(smraw + T_PEN1);

    const int bx = blockIdx.x;
    const int h  = blockIdx.y;
    const int b  = blockIdx.z;
    const int t  = threadIdx.x;
    const int lane = t & 31;
    const int wid  = t >> 5;

    const bool heavy = (bx >= 62);
    int qb, ch = 0;
    if (heavy) { int hx = bx - 62; qb = hx >> 3; ch = hx & 7; }
    else qb = bx + 2;

    const float rs  = 0.125f;
    const float pen = -10000.f;
    const size_t bh64 = ((size_t)(b * HH + h)) * SS * HDIM;

    {
        const __nv_bfloat16* qhp = g_qh + bh64 + (size_t)qb * BLKSZ * HDIM;
        const __nv_bfloat16* qlp = g_ql + bh64 + (size_t)qb * BLKSZ * HDIM;
        for (int i = t; i < 512; i += 128) {
            int row = i >> 3, seg = (i & 7) * 8;
            *(uint4*)(smraw + row * ATT_STRB + seg * 2)        = *(const uint4*)(qhp + row * HDIM + seg);
            *(uint4*)(smraw + 9216 + row * ATT_STRB + seg * 2) = *(const uint4*)(qlp + row * HDIM + seg);
        }
    }
    __syncthreads();

    uint32_t qfh[4][4], qfl[4][4];
    {
        const int lrow = lane & 15;
        const int lcol = (lane >> 4) * 8;
#pragma unroll
        for (int kk = 0; kk < 4; kk++) {
            uint32_t off = (uint32_t)((wid * 16 + lrow) * ATT_STRB + (kk * 16 + lcol) * 2);
            ldsm_x4(qfh[kk], smem_base + off);
            ldsm_x4(qfl[kk], smem_base + 9216 + off);
        }
    }
    __syncthreads();

    int nt;
    int kbs[5];
    bool is_band = false;
    if (heavy) {
        nt = 8;
    } else if (qb == NGB) {
        nt = 5; kbs[0]=0; kbs[1]=1; kbs[2]=2; kbs[3]=3; kbs[4]=4;
    } else if (qb == NB - 1) {
        nt = 5; kbs[0]=0; kbs[1]=1; kbs[2]=61; kbs[3]=62; kbs[4]=63;
    } else {
        nt = 5; kbs[0]=0; kbs[1]=1; kbs[2]=qb-1; kbs[3]=qb; kbs[4]=qb+1; is_band = true;
    }

#define KB_OF(IT) (heavy ? (ch * 8 + (IT)) : kbs[(IT)])

#define ISSUE_K(KB, STG) do {                                               \
    const __nv_bfloat16* khp_ = g_kh + bh64 + (size_t)(KB) * BLKSZ * HDIM;  \
    const __nv_bfloat16* klp_ = g_kl + bh64 + (size_t)(KB) * BLKSZ * HDIM;  \
    for (int i = t; i < 512; i += 128) {                                    \
        int row = i >> 3, seg = (i & 7) * 8;                                \
        uint32_t so = smem_base + KSTAGE(STG) + row * ATT_STRB + seg * 2;   \
        cp_async16(so,        khp_ + row * HDIM + seg);                     \
        cp_async16(so + 9216, klp_ + row * HDIM + seg);                     \
    }                                                                       \
    CP_COMMIT; } while (0)

#define ISSUE_VP(IT, KB, BANDT) do {                                        \
    const __nv_bfloat16* vhp_ = g_vh + bh64 + (size_t)(KB) * BLKSZ * HDIM;  \
    const __nv_bfloat16* vlp_ = g_vl + bh64 + (size_t)(KB) * BLKSZ * HDIM;  \
    for (int i = t; i < 512; i += 128) {                                    \
        int row = i >> 3, seg = (i & 7) * 8;                                \
        uint32_t so = smem_base + T_VH + row * ATT_STRB + seg * 2;          \
        cp_async16(so,        vhp_ + row * HDIM + seg);                     \
        cp_async16(so + 9216, vlp_ + row * HDIM + seg);                     \
    }                                                                       \
    if (BANDT) {                                                            \
        const float* bmb_ = band_mask                                       \
            + ((size_t)(b * 60 + (qb - 3)) * 64) * 192 + (size_t)((IT) - 2) * 64; \
        for (int i = t; i < 1024; i += 128) {                               \
            int row = i >> 4, c = i & 15;                                   \
            cp_async16(smem_base + T_PEN2 + row * 272 + c * 16,             \
                       bmb_ + row * 192 + c * 4);                           \
        }                                                                   \
    } else if (t < 16) {                                                    \
        cp_async16(smem_base + T_PEN1 + t * 16,                             \
                   to_mask + (size_t)b * SS + (KB) * BLKSZ + t * 4);        \
    }                                                                       \
    CP_COMMIT; } while (0)

    float m0 = -1e30f, m1 = -1e30f, l0 = 0.f, l1 = 0.f;
    float o[8][4];
#pragma unroll
    for (int nj = 0; nj < 8; nj++)
#pragma unroll
        for (int e = 0; e < 4; e++) o[nj][e] = 0.f;

    ISSUE_K(KB_OF(0), 0);

    for (int it = 0; it < nt; it++) {
        const int kb = KB_OF(it);
        const bool band_tile = (is_band && it >= 2);

        ISSUE_VP(it, kb, band_tile);
        if (it + 1 < nt) {
            ISSUE_K(KB_OF(it + 1), (it + 1) & 1);
            CP_WAIT2;
        } else {
            CP_WAIT1;
        }
        __syncthreads();

        const uint32_t kst = smem_base + KSTAGE(it & 1);
        float acc[8][4];
#pragma unroll
        for (int nj = 0; nj < 8; nj++)
#pragma unroll
            for (int e = 0; e < 4; e++) acc[nj][e] = 0.f;

#pragma unroll
        for (int nj = 0; nj < 8; nj++) {
            uint32_t kh8[8], kl8[8];
            uint32_t rbase = (uint32_t)((nj * 8 + (lane & 7)) * ATT_STRB + (lane >> 3) * 16);
            ldsm_x4(kh8,     kst + rbase);
            ldsm_x4(kh8 + 4, kst + rbase + 64);
            ldsm_x4(kl8,     kst + 9216 + rbase);
            ldsm_x4(kl8 + 4, kst + 9216 + rbase + 64);
#pragma unroll
            for (int kk = 0; kk < 4; kk++) {
                mma_bf16(acc[nj], qfh[kk], kh8[2*kk], kh8[2*kk+1]);
                mma_bf16(acc[nj], qfh[kk], kl8[2*kk], kl8[2*kk+1]);
                mma_bf16(acc[nj], qfl[kk], kh8[2*kk], kh8[2*kk+1]);
            }
        }

        if (it + 1 < nt) { CP_WAIT1; } else { CP_WAIT0; }
        __syncthreads();

        const int qr0 = wid * 16 + (lane >> 2);
#pragma unroll
        for (int nj = 0; nj < 8; nj++) {
#pragma unroll
            for (int e = 0; e < 4; e++) {
                int col = nj * 8 + (lane & 3) * 2 + (e & 1);
                float mv = band_tile
                    ? pen2f[(qr0 + (e >> 1) * 8) * 68 + col]
                    : pen1f[col];
                acc[nj][e] = acc[nj][e] * rs + (1.f - mv) * pen;
            }
        }

        float tm0 = -1e30f, tm1 = -1e30f;
#pragma unroll
        for (int nj = 0; nj < 8; nj++) {
            tm0 = fmaxf(tm0, fmaxf(acc[nj][0], acc[nj][1]));
            tm1 = fmaxf(tm1, fmaxf(acc[nj][2], acc[nj][3]));
        }
        tm0 = fmaxf(tm0, __shfl_xor_sync(0xffffffffu, tm0, 1));
        tm0 = fmaxf(tm0, __shfl_xor_sync(0xffffffffu, tm0, 2));
        tm1 = fmaxf(tm1, __shfl_xor_sync(0xffffffffu, tm1, 1));
        tm1 = fmaxf(tm1, __shfl_xor_sync(0xffffffffu, tm1, 2));

        float nm0 = fmaxf(m0, tm0), nm1 = fmaxf(m1, tm1);
        float c0 = __expf(m0 - nm0), c1 = __expf(m1 - nm1);
        float ts0 = 0.f, ts1 = 0.f;
#pragma unroll
        for (int nj = 0; nj < 8; nj++) {
            acc[nj][0] = __expf(acc[nj][0] - nm0);
            acc[nj][1] = __expf(acc[nj][1] - nm0);
            acc[nj][2] = __expf(acc[nj][2] - nm1);
            acc[nj][3] = __expf(acc[nj][3] - nm1);
            ts0 += acc[nj][0] + acc[nj][1];
            ts1 += acc[nj][2] + acc[nj][3];
        }
        ts0 += __shfl_xor_sync(0xffffffffu, ts0, 1);
        ts0 += __shfl_xor_sync(0xffffffffu, ts0, 2);
        ts1 += __shfl_xor_sync(0xffffffffu, ts1, 1);
        ts1 += __shfl_xor_sync(0xffffffffu, ts1, 2);
        l0 = l0 * c0 + ts0;  l1 = l1 * c1 + ts1;
        m0 = nm0;  m1 = nm1;
#pragma unroll
        for (int nj = 0; nj < 8; nj++) {
            o[nj][0] *= c0; o[nj][1] *= c0;
            o[nj][2] *= c1; o[nj][3] *= c1;
        }

        uint32_t phi[4][4], plo[4][4];
#pragma unroll
        for (int kk2 = 0; kk2 < 4; kk2++) {
            phi[kk2][0] = pack_hilo(acc[2*kk2][0],   acc[2*kk2][1],   plo[kk2][0]);
            phi[kk2][1] = pack_hilo(acc[2*kk2][2],   acc[2*kk2][3],   plo[kk2][1]);
            phi[kk2][2] = pack_hilo(acc[2*kk2+1][0], acc[2*kk2+1][1], plo[kk2][2]);
            phi[kk2][3] = pack_hilo(acc[2*kk2+1][2], acc[2*kk2+1][3], plo[kk2][3]);
        }

#pragma unroll
        for (int njd = 0; njd < 8; njd++) {
#pragma unroll
            for (int kk2 = 0; kk2 < 4; kk2++) {
                uint32_t vh[2], vl[2];
                uint32_t off = (uint32_t)((kk2 * 16 + (lane & 15)) * ATT_STRB + njd * 16);
                ldsm_x2_trans(vh, smem_base + T_VH + off);
                ldsm_x2_trans(vl, smem_base + T_VL + off);
                mma_bf16(o[njd], phi[kk2], vh[0], vh[1]);
                mma_bf16(o[njd], phi[kk2], vl[0], vl[1]);
                mma_bf16(o[njd], plo[kk2], vh[0], vh[1]);
            }
        }
        __syncthreads();
    }

    const int r0 = wid * 16 + (lane >> 2);
    if (!heavy) {
        const int s0 = qb * BLKSZ + r0;
        const int s1 = s0 + 8;
        float inv0 = from_mask[(size_t)b * SS + s0] / l0;
        float inv1 = from_mask[(size_t)b * SS + s1] / l1;
#pragma unroll
        for (int njd = 0; njd < 8; njd++) {
            const int col = njd * 8 + (lane & 3) * 2;
            {
                size_t idx = ((size_t)b * SS + s0) * DD + h * HDIM + col;
                uint32_t lo, hi = pack_hilo(o[njd][0] * inv0, o[njd][1] * inv0, lo);
                *(uint32_t*)(g_c_hi + idx) = hi;
                *(uint32_t*)(g_c_lo + idx) = lo;
            }
            {
                size_t idx = ((size_t)b * SS + s1) * DD + h * HDIM + col;
                uint32_t lo, hi = pack_hilo(o[njd][2] * inv1, o[njd][3] * inv1, lo);
                *(uint32_t*)(g_c_hi + idx) = hi;
                *(uint32_t*)(g_c_lo + idx) = lo;
            }
        }
    } else {
        const int cid = ((b * HH + h) * 2 + qb) * 8 + ch;
        float* pob = g_po + (size_t)cid * 4096;
#pragma unroll
        for (int njd = 0; njd < 8; njd++) {
            const int col = njd * 8 + (lane & 3) * 2;
            float2 s0v; s0v.x = o[njd][0]; s0v.y = o[njd][1];
            float2 s1v; s1v.x = o[njd][2]; s1v.y = o[njd][3];
            *(float2*)(pob + r0 * 64 + col) = s0v;
            *(float2*)(pob + (r0 + 8) * 64 + col) = s1v;
        }
        if ((lane & 3) == 0) {
            g_pm[cid * 64 + r0]     = m0;
            g_pm[cid * 64 + r0 + 8] = m1;
            g_pl[cid * 64 + r0]     = l0;
            g_pl[cid * 64 + r0 + 8] = l1;
        }
    }
}

// ---------------------------------------------------------------------------
// Combine split-KV partials for heavy q-blocks.
// ---------------------------------------------------------------------------
__global__ __launch_bounds__(128) void attn_combine(const float* __restrict__ from_mask)
{
    const int x  = blockIdx.x;
    const int qb = x & 1;
    const int h  = (x >> 1) & 15;
    const int b  = x >> 5;
    const int t  = threadIdx.x;
    const int r  = t >> 1;
    const int c0 = (t & 1) * 32;
    const int base8 = x * 8;

    float m[8], l[8], M = -1e30f;
#pragma unroll
    for (int i = 0; i < 8; i++) {
        m[i] = g_pm[(base8 + i) * 64 + r];
        l[i] = g_pl[(base8 + i) * 64 + r];
        M = fmaxf(M, m[i]);
    }
    float L = 0.f, sc[8];
#pragma unroll
    for (int i = 0; i < 8; i++) { sc[i] = __expf(m[i] - M); L += l[i] * sc[i]; }

    float acc[32];
#pragma unroll
    for (int c = 0; c < 32; c++) acc[c] = 0.f;
#pragma unroll
    for (int i = 0; i < 8; i++) {
        const float* p = g_po + (size_t)(base8 + i) * 4096 + r * 64 + c0;
        float s = sc[i];
#pragma unroll
        for (int c4 = 0; c4 < 8; c4++) {
            float4 v = *(const float4*)(p + c4 * 4);
            acc[c4*4+0] += s * v.x; acc[c4*4+1] += s * v.y;
            acc[c4*4+2] += s * v.z; acc[c4*4+3] += s * v.w;
        }
    }

    const int s_ = qb * BLKSZ + r;
    float inv = from_mask[(size_t)b * SS + s_] / L;
    size_t idx = ((size_t)b * SS + s_) * DD + h * HDIM + c0;
#pragma unroll
    for (int c = 0; c < 32; c += 2) {
        uint32_t lo, hi = pack_hilo(acc[c] * inv, acc[c+1] * inv, lo);
        *(uint32_t*)(g_c_hi + idx + c) = hi;
        *(uint32_t*)(g_c_lo + idx + c) = lo;
    }
}

// ---------------------------------------------------------------------------
extern "C" void kernel_launch(void* const* d_in, const int* in_sizes, int n_in,
                              void* d_out, int out_size)
{
    const float* tokens    = (const float*)d_in[0];
    const float* band_mask = (const float*)d_in[1];
    const float* from_mask = (const float*)d_in[2];
    const float* to_mask   = (const float*)d_in[3];
    const float* Wq        = (const float*)d_in[4];
    const float* Wk        = (const float*)d_in[5];
    const float* Wv        = (const float*)d_in[6];
    const float* Wu        = (const float*)d_in[7];
    const float* bu        = (const float*)d_in[8];
    float* out = (float*)d_out;

    cudaFuncSetAttribute(attn_kernel,
                         cudaFuncAttributeMaxDynamicSharedMemorySize, ATTN_SMEM_BYTES);
    cudaFuncSetAttribute(gemm_hmma_kernel,
                         cudaFuncAttributeMaxDynamicSharedMemorySize, GEMM_SMEM_BYTES);

    // 0) Precision-split inputs and weights
    split_x_kernel<<<(MROWS * DD / 4) / 256, 256>>>(tokens);
    wsplit_kernel<<<dim3(1024, 4), 256>>>(Wq, Wk, Wv, Wu);

    // 1) QKV projections (3-stage pipelined HMMA, staged coalesced epilogue)
    gemm_hmma_kernel<<<dim3(8, 64, 3), 256, GEMM_SMEM_BYTES>>>(0, nullptr, nullptr);

    // 2) Sparse attention (light + split-KV heavy in one grid, cp.async pipelined)
    attn_kernel<<<dim3(78, HH, BB), 128, ATTN_SMEM_BYTES>>>(band_mask, from_mask, to_mask);

    // 2b) Combine heavy partials
    attn_combine<<<64, 128>>>(from_mask);

    // 3) Output projection + bias (3-stage pipelined HMMA)
    gemm_hmma_kernel<<<dim3(8, 64, 1), 256, GEMM_SMEM_BYTES>>>(3, bu, out);
}

// round 14
// speedup vs baseline: 1.8092x; 1.0039x over previous
#include <cuda_runtime.h>
#include <cuda_bf16.h>
#include <cstdint>
#include <math.h>

#define BB 2
#define SS 4096
#define DD 1024
#define HH 16
#define BLKSZ 64
#define NB 64          // S / BLK
#define NGB 2          // G / BLK
#define HDIM 64        // D / H
#define MROWS (BB*SS)  // 8192

// ---------------------------------------------------------------------------
// Device scratch (no allocation allowed)
// ---------------------------------------------------------------------------
__device__ __nv_bfloat16 g_x_hi[(size_t)MROWS*DD];
__device__ __nv_bfloat16 g_x_lo[(size_t)MROWS*DD];
__device__ __nv_bfloat16 g_c_hi[(size_t)MROWS*DD];
__device__ __nv_bfloat16 g_c_lo[(size_t)MROWS*DD];
__device__ __nv_bfloat16 g_w_hi[(size_t)4*DD*DD];   // [w][k][n] (native layout)
__device__ __nv_bfloat16 g_w_lo[(size_t)4*DD*DD];
// Q/K/V head-split bf16 hi/lo: [b,h,s,64]
__device__ __nv_bfloat16 g_qh[(size_t)BB*HH*SS*HDIM];
__device__ __nv_bfloat16 g_ql[(size_t)BB*HH*SS*HDIM];
__device__ __nv_bfloat16 g_kh[(size_t)BB*HH*SS*HDIM];
__device__ __nv_bfloat16 g_kl[(size_t)BB*HH*SS*HDIM];
__device__ __nv_bfloat16 g_vh[(size_t)BB*HH*SS*HDIM];
__device__ __nv_bfloat16 g_vl[(size_t)BB*HH*SS*HDIM];
// split-KV partials for heavy q-blocks
__device__ float g_po[(size_t)512*4096];
__device__ float g_pm[512*64];
__device__ float g_pl[512*64];

// ---------------------------------------------------------------------------
// mma.sync / ldmatrix / cp.async helpers (generic sm_80+ PTX)
// ---------------------------------------------------------------------------
__device__ __forceinline__ uint32_t smem_u32(const void* p) {
    uint32_t a;
    asm("{ .reg .u64 t; cvta.to.shared.u64 t, %1; cvt.u32.u64 %0, t; }" : "=r"(a) : "l"(p));
    return a;
}
__device__ __forceinline__ void ldsm_x4(uint32_t* r, uint32_t addr) {
    asm volatile("ldmatrix.sync.aligned.m8n8.x4.shared.b16 {%0,%1,%2,%3}, [%4];"
        : "=r"(r[0]), "=r"(r[1]), "=r"(r[2]), "=r"(r[3]) : "r"(addr));
}
__device__ __forceinline__ void ldsm_x2_trans(uint32_t* r, uint32_t addr) {
    asm volatile("ldmatrix.sync.aligned.m8n8.x2.trans.shared.b16 {%0,%1}, [%2];"
        : "=r"(r[0]), "=r"(r[1]) : "r"(addr));
}
__device__ __forceinline__ void mma_bf16(float (&c)[4], const uint32_t* a,
                                         uint32_t b0, uint32_t b1) {
    asm volatile("mma.sync.aligned.m16n8k16.row.col.f32.bf16.bf16.f32 "
        "{%0,%1,%2,%3}, {%4,%5,%6,%7}, {%8,%9}, {%0,%1,%2,%3};"
        : "+f"(c[0]), "+f"(c[1]), "+f"(c[2]), "+f"(c[3])
        : "r"(a[0]), "r"(a[1]), "r"(a[2]), "r"(a[3]), "r"(b0), "r"(b1));
}
__device__ __forceinline__ void cp_async16(uint32_t saddr, const void* gptr) {
    asm volatile("cp.async.cg.shared.global [%0], [%1], 16;" :: "r"(saddr), "l"(gptr));
}
#define CP_COMMIT asm volatile("cp.async.commit_group;")
#define CP_WAIT2  asm volatile("cp.async.wait_group 2;")
#define CP_WAIT1  asm volatile("cp.async.wait_group 1;")
#define CP_WAIT0  asm volatile("cp.async.wait_group 0;")

// pack two floats -> bf16x2 hi, bf16x2 lo (residual)
__device__ __forceinline__ uint32_t pack_hilo(float a, float b, uint32_t& lo_out) {
    __nv_bfloat162 h; h.x = __float2bfloat16(a); h.y = __float2bfloat16(b);
    __nv_bfloat162 l;
    l.x = __float2bfloat16(a - __bfloat162float(h.x));
    l.y = __float2bfloat16(b - __bfloat162float(h.y));
    lo_out = *(uint32_t*)&l;
    return *(uint32_t*)&h;
}

// ---------------------------------------------------------------------------
// Split tokens into bf16 hi/lo
// ---------------------------------------------------------------------------
__global__ __launch_bounds__(256) void split_x_kernel(const float* __restrict__ X)
{
    size_t i = (size_t)blockIdx.x * 256 + threadIdx.x;
    float4 v = ((const float4*)X)[i];
    float vs[4] = {v.x, v.y, v.z, v.w};
#pragma unroll
    for (int j = 0; j < 4; j++) {
        __nv_bfloat16 hi = __float2bfloat16(vs[j]);
        float lo = vs[j] - __bfloat162float(hi);
        g_x_hi[i * 4 + j] = hi;
        g_x_lo[i * 4 + j] = __float2bfloat16(lo);
    }
}

// ---------------------------------------------------------------------------
// Elementwise weight split (native [k][n] layout)
// ---------------------------------------------------------------------------
__global__ __launch_bounds__(256) void wsplit_kernel(
    const float* __restrict__ Wq, const float* __restrict__ Wk,
    const float* __restrict__ Wv, const float* __restrict__ Wu)
{
    const int w = blockIdx.y;
    const float* W = (w == 0) ? Wq : (w == 1) ? Wk : (w == 2) ? Wv : Wu;
    size_t i = (size_t)blockIdx.x * 256 + threadIdx.x;
    float4 v = ((const float4*)W)[i];
    float vs[4] = {v.x, v.y, v.z, v.w};
    size_t base = (size_t)w * DD * DD + i * 4;
#pragma unroll
    for (int j = 0; j < 4; j++) {
        __nv_bfloat16 hi = __float2bfloat16(vs[j]);
        float lo = vs[j] - __bfloat162float(hi);
        g_w_hi[base + j] = hi;
        g_w_lo[base + j] = __float2bfloat16(lo);
    }
}

// ---------------------------------------------------------------------------
// Split-bf16 HMMA GEMM, 3-stage cp.async pipeline (R13-proven).
// mode<3 epilogue staged through smem for coalesced 16B stores.
// ---------------------------------------------------------------------------
#define GK 32
#define SA2 40            // A stride (b16): 32 + 8 pad
#define SB2 136           // B stride (b16)
#define SA_HI_B 0
#define SA_LO_B 10240     // 128*40*2
#define SB_HI_B 20480
#define SB_LO_B 29184
#define STAGE_B 37888
#define NSTAGE 3
#define GEMM_SMEM_BYTES (NSTAGE*STAGE_B)
#define EP_STR 136
#define EP_HI 0
#define EP_LO (128*EP_STR*2)

__global__ __launch_bounds__(256, 2) void gemm_hmma_kernel(
    int mode_base, const float* __restrict__ bias, float* __restrict__ out_ptr)
{
    extern __shared__ __align__(16) char gsm[];
    const uint32_t smem_base = smem_u32(gsm);

    const int t    = threadIdx.x;
    const int lane = t & 31;
    const int wid  = t >> 5;
    const int wm   = wid & 3;
    const int wn   = wid >> 2;
    const int mode = mode_base + blockIdx.z;

    const int n0 = blockIdx.x * 128;
    const int m0 = blockIdx.y * 128;

    const __nv_bfloat16* Ahi = (mode < 3) ? g_x_hi : g_c_hi;
    const __nv_bfloat16* Alo = (mode < 3) ? g_x_lo : g_c_lo;
    const __nv_bfloat16* Bhi = g_w_hi + (size_t)mode * DD * DD;
    const __nv_bfloat16* Blo = g_w_lo + (size_t)mode * DD * DD;

    float acc[2][8][4];
#pragma unroll
    for (int mi = 0; mi < 2; mi++)
#pragma unroll
        for (int nj = 0; nj < 8; nj++)
#pragma unroll
            for (int e = 0; e < 4; e++) acc[mi][nj][e] = 0.f;

    const int lrow = lane & 15;
    const int lcol = (lane >> 4) * 8;

    const int arow0 = t >> 2,          aseg0 = (t & 3) * 8;
    const int arow1 = (t + 256) >> 2,  aseg1 = ((t + 256) & 3) * 8;
    const int brow0 = t >> 4,          bseg0 = (t & 15) * 8;
    const int brow1 = (t + 256) >> 4,  bseg1 = ((t + 256) & 15) * 8;

#define GEMM_PREFETCH(KC, SBUF) do {                                        \
    const int k0_ = (KC) * GK;                                              \
    const uint32_t sb_ = smem_base + (uint32_t)(SBUF) * STAGE_B;            \
    {   size_t go = (size_t)(m0 + arow0) * DD + k0_ + aseg0;                \
        uint32_t so = sb_ + (uint32_t)(arow0 * SA2 + aseg0) * 2;            \
        cp_async16(so + SA_HI_B, Ahi + go);                                 \
        cp_async16(so + SA_LO_B, Alo + go); }                               \
    {   size_t go = (size_t)(m0 + arow1) * DD + k0_ + aseg1;                \
        uint32_t so = sb_ + (uint32_t)(arow1 * SA2 + aseg1) * 2;            \
        cp_async16(so + SA_HI_B, Ahi + go);                                 \
        cp_async16(so + SA_LO_B, Alo + go); }                               \
    {   size_t go = (size_t)(k0_ + brow0) * DD + n0 + bseg0;                \
        uint32_t so = sb_ + (uint32_t)(brow0 * SB2 + bseg0) * 2;            \
        cp_async16(so + SB_HI_B, Bhi + go);                                 \
        cp_async16(so + SB_LO_B, Blo + go); }                               \
    {   size_t go = (size_t)(k0_ + brow1) * DD + n0 + bseg1;                \
        uint32_t so = sb_ + (uint32_t)(brow1 * SB2 + bseg1) * 2;            \
        cp_async16(so + SB_HI_B, Bhi + go);                                 \
        cp_async16(so + SB_LO_B, Blo + go); }                               \
    CP_COMMIT; } while (0)

    GEMM_PREFETCH(0, 0);
    GEMM_PREFETCH(1, 1);

    int cs = 0;
    int ps = 2;
    for (int kc = 0; kc < 32; kc++) {
        if (kc <= 29) { CP_WAIT1; } else { CP_WAIT0; }
        __syncthreads();
        if (kc + 2 < 32) {
            GEMM_PREFETCH(kc + 2, ps);
            ps = (ps + 1 == NSTAGE) ? 0 : ps + 1;
        }

        const uint32_t sb = smem_base + (uint32_t)cs * STAGE_B;
        cs = (cs + 1 == NSTAGE) ? 0 : cs + 1;
#pragma unroll
        for (int kk = 0; kk < 2; kk++) {
            uint32_t ah[2][4], al[2][4];
#pragma unroll
            for (int mi = 0; mi < 2; mi++) {
                uint32_t off = (uint32_t)((wm * 32 + mi * 16 + lrow) * SA2 + kk * 16 + lcol) * 2;
                ldsm_x4(ah[mi], sb + SA_HI_B + off);
                ldsm_x4(al[mi], sb + SA_LO_B + off);
            }
            uint32_t bh[8][2], bl[8][2];
#pragma unroll
            for (int nj = 0; nj < 8; nj++) {
                uint32_t off = (uint32_t)((kk * 16 + lrow) * SB2 + wn * 64 + nj * 8) * 2;
                ldsm_x2_trans(bh[nj], sb + SB_HI_B + off);
                ldsm_x2_trans(bl[nj], sb + SB_LO_B + off);
            }
#pragma unroll
            for (int mi = 0; mi < 2; mi++)
#pragma unroll
                for (int nj = 0; nj < 8; nj++) {
                    mma_bf16(acc[mi][nj], ah[mi], bh[nj][0], bh[nj][1]);
                    mma_bf16(acc[mi][nj], ah[mi], bl[nj][0], bl[nj][1]);
                    mma_bf16(acc[mi][nj], al[mi], bh[nj][0], bh[nj][1]);
                }
        }
    }

    if (mode < 3) {
        __syncthreads();
#pragma unroll
        for (int mi = 0; mi < 2; mi++) {
            const int rl0 = wm * 32 + mi * 16 + (lane >> 2);
#pragma unroll
            for (int nj = 0; nj < 8; nj++) {
                const int cl = wn * 64 + nj * 8 + (lane & 3) * 2;
#pragma unroll
                for (int half = 0; half < 2; half++) {
                    const int rl = rl0 + half * 8;
                    uint32_t lo, hi = pack_hilo(acc[mi][nj][half * 2 + 0],
                                                acc[mi][nj][half * 2 + 1], lo);
                    uint32_t off = (uint32_t)(rl * EP_STR + cl) * 2;
                    *(uint32_t*)(gsm + EP_HI + off) = hi;
                    *(uint32_t*)(gsm + EP_LO + off) = lo;
                }
            }
        }
        __syncthreads();

        __nv_bfloat16* Oh = (mode == 0) ? g_qh : (mode == 1) ? g_kh : g_vh;
        __nv_bfloat16* Ol = (mode == 0) ? g_ql : (mode == 1) ? g_kl : g_vl;
        for (int i = t; i < 2048; i += 256) {
            const int row = i >> 4;
            const int col = (i & 15) * 8;
            const int r   = m0 + row;
            const int b_  = r >> 12, s = r & 4095;
            const int h   = (n0 + col) >> 6;
            const int dd  = col & 63;
            size_t gidx = (((size_t)(b_ * HH + h)) * SS + s) * HDIM + dd;
            uint32_t soff = (uint32_t)(row * EP_STR + col) * 2;
            *(uint4*)(Oh + gidx) = *(const uint4*)(gsm + EP_HI + soff);
            *(uint4*)(Ol + gidx) = *(const uint4*)(gsm + EP_LO + soff);
        }
    } else {
#pragma unroll
        for (int mi = 0; mi < 2; mi++) {
            const int r0 = m0 + wm * 32 + mi * 16 + (lane >> 2);
#pragma unroll
            for (int nj = 0; nj < 8; nj++) {
                const int col = wn * 64 + nj * 8 + (lane & 3) * 2;
                float bv0 = bias[n0 + col], bv1 = bias[n0 + col + 1];
                float2 st0; st0.x = acc[mi][nj][0] + bv0; st0.y = acc[mi][nj][1] + bv1;
                float2 st1; st1.x = acc[mi][nj][2] + bv0; st1.y = acc[mi][nj][3] + bv1;
                *(float2*)(out_ptr + (size_t)r0 * DD + n0 + col) = st0;
                *(float2*)(out_ptr + (size_t)(r0 + 8) * DD + n0 + col) = st1;
            }
        }
    }
}

// ---------------------------------------------------------------------------
// BigBird sparse attention (R13-proven mainloop). Grid ordering changed:
// HEAVY CTAs FIRST (bx < 16: qb = bx>>3, chunk = bx&7) so the longest
// (8-tile) CTAs launch in wave 1; light CTAs (bx >= 16, qb = bx - 14) fill in.
// ---------------------------------------------------------------------------
#define ATT_STRB 144
#define KSTAGE(s) ((s) * 18432)
#define T_VH 36864
#define T_VL 46080
#define T_PEN2 55296
#define T_PEN1 72704
#define ATTN_SMEM_BYTES 72976

__global__ __launch_bounds__(128, 3) void attn_kernel(
    const float* __restrict__ band_mask,
    const float* __restrict__ from_mask,
    const float* __restrict__ to_mask)
{
    extern __shared__ __align__(16) char smraw[];
    const uint32_t smem_base = smem_u32(smraw);
    const float* pen2f = (const float*)(smraw + T_PEN2);
    const float* pen1f = (const float*)(smraw + T_PEN1);

    const int bx = blockIdx.x;
    const int h  = blockIdx.y;
    const int b  = blockIdx.z;
    const int t  = threadIdx.x;
    const int lane = t & 31;
    const int wid  = t >> 5;

    // heavy first: bx in [0,16) -> qb = bx>>3 (0..1), chunk = bx&7
    const bool heavy = (bx < 16);
    int qb, ch = 0;
    if (heavy) { qb = bx >> 3; ch = bx & 7; }
    else qb = bx - 14;          // bx in [16,78) -> qb in [2,64)

    const float rs  = 0.125f;
    const float pen = -10000.f;
    const size_t bh64 = ((size_t)(b * HH + h)) * SS * HDIM;

    {
        const __nv_bfloat16* qhp = g_qh + bh64 + (size_t)qb * BLKSZ * HDIM;
        const __nv_bfloat16* qlp = g_ql + bh64 + (size_t)qb * BLKSZ * HDIM;
        for (int i = t; i < 512; i += 128) {
            int row = i >> 3, seg = (i & 7) * 8;
            *(uint4*)(smraw + row * ATT_STRB + seg * 2)        = *(const uint4*)(qhp + row * HDIM + seg);
            *(uint4*)(smraw + 9216 + row * ATT_STRB + seg * 2) = *(const uint4*)(qlp + row * HDIM + seg);
        }
    }
    __syncthreads();

    uint32_t qfh[4][4], qfl[4][4];
    {
        const int lrow = lane & 15;
        const int lcol = (lane >> 4) * 8;
#pragma unroll
        for (int kk = 0; kk < 4; kk++) {
            uint32_t off = (uint32_t)((wid * 16 + lrow) * ATT_STRB + (kk * 16 + lcol) * 2);
            ldsm_x4(qfh[kk], smem_base + off);
            ldsm_x4(qfl[kk], smem_base + 9216 + off);
        }
    }
    __syncthreads();

    int nt;
    int kbs[5];
    bool is_band = false;
    if (heavy) {
        nt = 8;
    } else if (qb == NGB) {
        nt = 5; kbs[0]=0; kbs[1]=1; kbs[2]=2; kbs[3]=3; kbs[4]=4;
    } else if (qb == NB - 1) {
        nt = 5; kbs[0]=0; kbs[1]=1; kbs[2]=61; kbs[3]=62; kbs[4]=63;
    } else {
        nt = 5; kbs[0]=0; kbs[1]=1; kbs[2]=qb-1; kbs[3]=qb; kbs[4]=qb+1; is_band = true;
    }

#define KB_OF(IT) (heavy ? (ch * 8 + (IT)) : kbs[(IT)])

#define ISSUE_K(KB, STG) do {                                               \
    const __nv_bfloat16* khp_ = g_kh + bh64 + (size_t)(KB) * BLKSZ * HDIM;  \
    const __nv_bfloat16* klp_ = g_kl + bh64 + (size_t)(KB) * BLKSZ * HDIM;  \
    for (int i = t; i < 512; i += 128) {                                    \
        int row = i >> 3, seg = (i & 7) * 8;                                \
        uint32_t so = smem_base + KSTAGE(STG) + row * ATT_STRB + seg * 2;   \
        cp_async16(so,        khp_ + row * HDIM + seg);                     \
        cp_async16(so + 9216, klp_ + row * HDIM + seg);                     \
    }                                                                       \
    CP_COMMIT; } while (0)

#define ISSUE_VP(IT, KB, BANDT) do {                                        \
    const __nv_bfloat16* vhp_ = g_vh + bh64 + (size_t)(KB) * BLKSZ * HDIM;  \
    const __nv_bfloat16* vlp_ = g_vl + bh64 + (size_t)(KB) * BLKSZ * HDIM;  \
    for (int i = t; i < 512; i += 128) {                                    \
        int row = i >> 3, seg = (i & 7) * 8;                                \
        uint32_t so = smem_base + T_VH + row * ATT_STRB + seg * 2;          \
        cp_async16(so,        vhp_ + row * HDIM + seg);                     \
        cp_async16(so + 9216, vlp_ + row * HDIM + seg);                     \
    }                                                                       \
    if (BANDT) {                                                            \
        const float* bmb_ = band_mask                                       \
            + ((size_t)(b * 60 + (qb - 3)) * 64) * 192 + (size_t)((IT) - 2) * 64; \
        for (int i = t; i < 1024; i += 128) {                               \
            int row = i >> 4, c = i & 15;                                   \
            cp_async16(smem_base + T_PEN2 + row * 272 + c * 16,             \
                       bmb_ + row * 192 + c * 4);                           \
        }                                                                   \
    } else if (t < 16) {                                                    \
        cp_async16(smem_base + T_PEN1 + t * 16,                             \
                   to_mask + (size_t)b * SS + (KB) * BLKSZ + t * 4);        \
    }                                                                       \
    CP_COMMIT; } while (0)

    float m0 = -1e30f, m1 = -1e30f, l0 = 0.f, l1 = 0.f;
    float o[8][4];
#pragma unroll
    for (int nj = 0; nj < 8; nj++)
#pragma unroll
        for (int e = 0; e < 4; e++) o[nj][e] = 0.f;

    ISSUE_K(KB_OF(0), 0);

    for (int it = 0; it < nt; it++) {
        const int kb = KB_OF(it);
        const bool band_tile = (is_band && it >= 2);

        ISSUE_VP(it, kb, band_tile);
        if (it + 1 < nt) {
            ISSUE_K(KB_OF(it + 1), (it + 1) & 1);
            CP_WAIT2;
        } else {
            CP_WAIT1;
        }
        __syncthreads();

        const uint32_t kst = smem_base + KSTAGE(it & 1);
        float acc[8][4];
#pragma unroll
        for (int nj = 0; nj < 8; nj++)
#pragma unroll
            for (int e = 0; e < 4; e++) acc[nj][e] = 0.f;

#pragma unroll
        for (int nj = 0; nj < 8; nj++) {
            uint32_t kh8[8], kl8[8];
            uint32_t rbase = (uint32_t)((nj * 8 + (lane & 7)) * ATT_STRB + (lane >> 3) * 16);
            ldsm_x4(kh8,     kst + rbase);
            ldsm_x4(kh8 + 4, kst + rbase + 64);
            ldsm_x4(kl8,     kst + 9216 + rbase);
            ldsm_x4(kl8 + 4, kst + 9216 + rbase + 64);
#pragma unroll
            for (int kk = 0; kk < 4; kk++) {
                mma_bf16(acc[nj], qfh[kk], kh8[2*kk], kh8[2*kk+1]);
                mma_bf16(acc[nj], qfh[kk], kl8[2*kk], kl8[2*kk+1]);
                mma_bf16(acc[nj], qfl[kk], kh8[2*kk], kh8[2*kk+1]);
            }
        }

        if (it + 1 < nt) { CP_WAIT1; } else { CP_WAIT0; }
        __syncthreads();

        const int qr0 = wid * 16 + (lane >> 2);
#pragma unroll
        for (int nj = 0; nj < 8; nj++) {
#pragma unroll
            for (int e = 0; e < 4; e++) {
                int col = nj * 8 + (lane & 3) * 2 + (e & 1);
                float mv = band_tile
                    ? pen2f[(qr0 + (e >> 1) * 8) * 68 + col]
                    : pen1f[col];
                acc[nj][e] = acc[nj][e] * rs + (1.f - mv) * pen;
            }
        }

        float tm0 = -1e30f, tm1 = -1e30f;
#pragma unroll
        for (int nj = 0; nj < 8; nj++) {
            tm0 = fmaxf(tm0, fmaxf(acc[nj][0], acc[nj][1]));
            tm1 = fmaxf(tm1, fmaxf(acc[nj][2], acc[nj][3]));
        }
        tm0 = fmaxf(tm0, __shfl_xor_sync(0xffffffffu, tm0, 1));
        tm0 = fmaxf(tm0, __shfl_xor_sync(0xffffffffu, tm0, 2));
        tm1 = fmaxf(tm1, __shfl_xor_sync(0xffffffffu, tm1, 1));
        tm1 = fmaxf(tm1, __shfl_xor_sync(0xffffffffu, tm1, 2));

        float nm0 = fmaxf(m0, tm0), nm1 = fmaxf(m1, tm1);
        float c0 = __expf(m0 - nm0), c1 = __expf(m1 - nm1);
        float ts0 = 0.f, ts1 = 0.f;
#pragma unroll
        for (int nj = 0; nj < 8; nj++) {
            acc[nj][0] = __expf(acc[nj][0] - nm0);
            acc[nj][1] = __expf(acc[nj][1] - nm0);
            acc[nj][2] = __expf(acc[nj][2] - nm1);
            acc[nj][3] = __expf(acc[nj][3] - nm1);
            ts0 += acc[nj][0] + acc[nj][1];
            ts1 += acc[nj][2] + acc[nj][3];
        }
        ts0 += __shfl_xor_sync(0xffffffffu, ts0, 1);
        ts0 += __shfl_xor_sync(0xffffffffu, ts0, 2);
        ts1 += __shfl_xor_sync(0xffffffffu, ts1, 1);
        ts1 += __shfl_xor_sync(0xffffffffu, ts1, 2);
        l0 = l0 * c0 + ts0;  l1 = l1 * c1 + ts1;
        m0 = nm0;  m1 = nm1;
#pragma unroll
        for (int nj = 0; nj < 8; nj++) {
            o[nj][0] *= c0; o[nj][1] *= c0;
            o[nj][2] *= c1; o[nj][3] *= c1;
        }

        uint32_t phi[4][4], plo[4][4];
#pragma unroll
        for (int kk2 = 0; kk2 < 4; kk2++) {
            phi[kk2][0] = pack_hilo(acc[2*kk2][0],   acc[2*kk2][1],   plo[kk2][0]);
            phi[kk2][1] = pack_hilo(acc[2*kk2][2],   acc[2*kk2][3],   plo[kk2][1]);
            phi[kk2][2] = pack_hilo(acc[2*kk2+1][0], acc[2*kk2+1][1], plo[kk2][2]);
            phi[kk2][3] = pack_hilo(acc[2*kk2+1][2], acc[2*kk2+1][3], plo[kk2][3]);
        }

#pragma unroll
        for (int njd = 0; njd < 8; njd++) {
#pragma unroll
            for (int kk2 = 0; kk2 < 4; kk2++) {
                uint32_t vh[2], vl[2];
                uint32_t off = (uint32_t)((kk2 * 16 + (lane & 15)) * ATT_STRB + njd * 16);
                ldsm_x2_trans(vh, smem_base + T_VH + off);
                ldsm_x2_trans(vl, smem_base + T_VL + off);
                mma_bf16(o[njd], phi[kk2], vh[0], vh[1]);
                mma_bf16(o[njd], phi[kk2], vl[0], vl[1]);
                mma_bf16(o[njd], plo[kk2], vh[0], vh[1]);
            }
        }
        __syncthreads();
    }

    const int r0 = wid * 16 + (lane >> 2);
    if (!heavy) {
        const int s0 = qb * BLKSZ + r0;
        const int s1 = s0 + 8;
        float inv0 = from_mask[(size_t)b * SS + s0] / l0;
        float inv1 = from_mask[(size_t)b * SS + s1] / l1;
#pragma unroll
        for (int njd = 0; njd < 8; njd++) {
            const int col = njd * 8 + (lane & 3) * 2;
            {
                size_t idx = ((size_t)b * SS + s0) * DD + h * HDIM + col;
                uint32_t lo, hi = pack_hilo(o[njd][0] * inv0, o[njd][1] * inv0, lo);
                *(uint32_t*)(g_c_hi + idx) = hi;
                *(uint32_t*)(g_c_lo + idx) = lo;
            }
            {
                size_t idx = ((size_t)b * SS + s1) * DD + h * HDIM + col;
                uint32_t lo, hi = pack_hilo(o[njd][2] * inv1, o[njd][3] * inv1, lo);
                *(uint32_t*)(g_c_hi + idx) = hi;
                *(uint32_t*)(g_c_lo + idx) = lo;
            }
        }
    } else {
        const int cid = ((b * HH + h) * 2 + qb) * 8 + ch;
        float* pob = g_po + (size_t)cid * 4096;
#pragma unroll
        for (int njd = 0; njd < 8; njd++) {
            const int col = njd * 8 + (lane & 3) * 2;
            float2 s0v; s0v.x = o[njd][0]; s0v.y = o[njd][1];
            float2 s1v; s1v.x = o[njd][2]; s1v.y = o[njd][3];
            *(float2*)(pob + r0 * 64 + col) = s0v;
            *(float2*)(pob + (r0 + 8) * 64 + col) = s1v;
        }
        if ((lane & 3) == 0) {
            g_pm[cid * 64 + r0]     = m0;
            g_pm[cid * 64 + r0 + 8] = m1;
            g_pl[cid * 64 + r0]     = l0;
            g_pl[cid * 64 + r0 + 8] = l1;
        }
    }
}

// ---------------------------------------------------------------------------
// Combine split-KV partials for heavy q-blocks.
// ---------------------------------------------------------------------------
__global__ __launch_bounds__(128) void attn_combine(const float* __restrict__ from_mask)
{
    const int x  = blockIdx.x;
    const int qb = x & 1;
    const int h  = (x >> 1) & 15;
    const int b  = x >> 5;
    const int t  = threadIdx.x;
    const int r  = t >> 1;
    const int c0 = (t & 1) * 32;
    const int base8 = x * 8;

    float m[8], l[8], M = -1e30f;
#pragma unroll
    for (int i = 0; i < 8; i++) {
        m[i] = g_pm[(base8 + i) * 64 + r];
        l[i] = g_pl[(base8 + i) * 64 + r];
        M = fmaxf(M, m[i]);
    }
    float L = 0.f, sc[8];
#pragma unroll
    for (int i = 0; i < 8; i++) { sc[i] = __expf(m[i] - M); L += l[i] * sc[i]; }

    float acc[32];
#pragma unroll
    for (int c = 0; c < 32; c++) acc[c] = 0.f;
#pragma unroll
    for (int i = 0; i < 8; i++) {
        const float* p = g_po + (size_t)(base8 + i) * 4096 + r * 64 + c0;
        float s = sc[i];
#pragma unroll
        for (int c4 = 0; c4 < 8; c4++) {
            float4 v = *(const float4*)(p + c4 * 4);
            acc[c4*4+0] += s * v.x; acc[c4*4+1] += s * v.y;
            acc[c4*4+2] += s * v.z; acc[c4*4+3] += s * v.w;
        }
    }

    const int s_ = qb * BLKSZ + r;
    float inv = from_mask[(size_t)b * SS + s_] / L;
    size_t idx = ((size_t)b * SS + s_) * DD + h * HDIM + c0;
#pragma unroll
    for (int c = 0; c < 32; c += 2) {
        uint32_t lo, hi = pack_hilo(acc[c] * inv, acc[c+1] * inv, lo);
        *(uint32_t*)(g_c_hi + idx + c) = hi;
        *(uint32_t*)(g_c_lo + idx + c) = lo;
    }
}

// ---------------------------------------------------------------------------
extern "C" void kernel_launch(void* const* d_in, const int* in_sizes, int n_in,
                              void* d_out, int out_size)
{
    const float* tokens    = (const float*)d_in[0];
    const float* band_mask = (const float*)d_in[1];
    const float* from_mask = (const float*)d_in[2];
    const float* to_mask   = (const float*)d_in[3];
    const float* Wq        = (const float*)d_in[4];
    const float* Wk        = (const float*)d_in[5];
    const float* Wv        = (const float*)d_in[6];
    const float* Wu        = (const float*)d_in[7];
    const float* bu        = (const float*)d_in[8];
    float* out = (float*)d_out;

    cudaFuncSetAttribute(attn_kernel,
                         cudaFuncAttributeMaxDynamicSharedMemorySize, ATTN_SMEM_BYTES);
    cudaFuncSetAttribute(gemm_hmma_kernel,
                         cudaFuncAttributeMaxDynamicSharedMemorySize, GEMM_SMEM_BYTES);

    // 0) Precision-split inputs and weights
    split_x_kernel<<<(MROWS * DD / 4) / 256, 256>>>(tokens);
    wsplit_kernel<<<dim3(1024, 4), 256>>>(Wq, Wk, Wv, Wu);

    // 1) QKV projections (3-stage pipelined HMMA, staged coalesced epilogue)
    gemm_hmma_kernel<<<dim3(8, 64, 3), 256, GEMM_SMEM_BYTES>>>(0, nullptr, nullptr);

    // 2) Sparse attention (heavy CTAs first in grid order)
    attn_kernel<<<dim3(78, HH, BB), 128, ATTN_SMEM_BYTES>>>(band_mask, from_mask, to_mask);

    // 2b) Combine heavy partials
    attn_combine<<<64, 128>>>(from_mask);

    // 3) Output projection + bias (3-stage pipelined HMMA)
    gemm_hmma_kernel<<<dim3(8, 64, 1), 256, GEMM_SMEM_BYTES>>>(3, bu, out);
}

// round 15
// speedup vs baseline: 1.8763x; 1.0371x over previous
#include <cuda_runtime.h>
#include <cuda_bf16.h>
#include <cstdint>
#include <math.h>

#define BB 2
#define SS 4096
#define DD 1024
#define HH 16
#define BLKSZ 64
#define NB 64          // S / BLK
#define NGB 2          // G / BLK
#define HDIM 64        // D / H
#define MROWS (BB*SS)  // 8192

// ---------------------------------------------------------------------------
// Device scratch (no allocation allowed)
// ---------------------------------------------------------------------------
__device__ __nv_bfloat16 g_x_hi[(size_t)MROWS*DD];
__device__ __nv_bfloat16 g_x_lo[(size_t)MROWS*DD];
__device__ __nv_bfloat16 g_c_hi[(size_t)MROWS*DD];
__device__ __nv_bfloat16 g_c_lo[(size_t)MROWS*DD];
__device__ __nv_bfloat16 g_w_hi[(size_t)4*DD*DD];   // [w][k][n] (native layout)
__device__ __nv_bfloat16 g_w_lo[(size_t)4*DD*DD];
// Q/K/V head-split bf16 hi/lo: [b,h,s,64]
__device__ __nv_bfloat16 g_qh[(size_t)BB*HH*SS*HDIM];
__device__ __nv_bfloat16 g_ql[(size_t)BB*HH*SS*HDIM];
__device__ __nv_bfloat16 g_kh[(size_t)BB*HH*SS*HDIM];
__device__ __nv_bfloat16 g_kl[(size_t)BB*HH*SS*HDIM];
__device__ __nv_bfloat16 g_vh[(size_t)BB*HH*SS*HDIM];
__device__ __nv_bfloat16 g_vl[(size_t)BB*HH*SS*HDIM];
// split-KV partials for heavy q-blocks
__device__ float g_po[(size_t)512*4096];
__device__ float g_pm[512*64];
__device__ float g_pl[512*64];

// ---------------------------------------------------------------------------
// mma.sync / ldmatrix / cp.async helpers (generic sm_80+ PTX)
// ---------------------------------------------------------------------------
__device__ __forceinline__ uint32_t smem_u32(const void* p) {
    uint32_t a;
    asm("{ .reg .u64 t; cvta.to.shared.u64 t, %1; cvt.u32.u64 %0, t; }" : "=r"(a) : "l"(p));
    return a;
}
__device__ __forceinline__ void ldsm_x4(uint32_t* r, uint32_t addr) {
    asm volatile("ldmatrix.sync.aligned.m8n8.x4.shared.b16 {%0,%1,%2,%3}, [%4];"
        : "=r"(r[0]), "=r"(r[1]), "=r"(r[2]), "=r"(r[3]) : "r"(addr));
}
__device__ __forceinline__ void ldsm_x2_trans(uint32_t* r, uint32_t addr) {
    asm volatile("ldmatrix.sync.aligned.m8n8.x2.trans.shared.b16 {%0,%1}, [%2];"
        : "=r"(r[0]), "=r"(r[1]) : "r"(addr));
}
__device__ __forceinline__ void mma_bf16(float (&c)[4], const uint32_t* a,
                                         uint32_t b0, uint32_t b1) {
    asm volatile("mma.sync.aligned.m16n8k16.row.col.f32.bf16.bf16.f32 "
        "{%0,%1,%2,%3}, {%4,%5,%6,%7}, {%8,%9}, {%0,%1,%2,%3};"
        : "+f"(c[0]), "+f"(c[1]), "+f"(c[2]), "+f"(c[3])
        : "r"(a[0]), "r"(a[1]), "r"(a[2]), "r"(a[3]), "r"(b0), "r"(b1));
}
__device__ __forceinline__ void cp_async16(uint32_t saddr, const void* gptr) {
    asm volatile("cp.async.cg.shared.global [%0], [%1], 16;" :: "r"(saddr), "l"(gptr));
}
#define CP_COMMIT asm volatile("cp.async.commit_group;")
#define CP_WAIT2  asm volatile("cp.async.wait_group 2;")
#define CP_WAIT1  asm volatile("cp.async.wait_group 1;")
#define CP_WAIT0  asm volatile("cp.async.wait_group 0;")

// pack two floats -> bf16x2 hi, bf16x2 lo (residual)
__device__ __forceinline__ uint32_t pack_hilo(float a, float b, uint32_t& lo_out) {
    __nv_bfloat162 h; h.x = __float2bfloat16(a); h.y = __float2bfloat16(b);
    __nv_bfloat162 l;
    l.x = __float2bfloat16(a - __bfloat162float(h.x));
    l.y = __float2bfloat16(b - __bfloat162float(h.y));
    lo_out = *(uint32_t*)&l;
    return *(uint32_t*)&h;
}

// ---------------------------------------------------------------------------
// Fused precision-split prep: blocks [0, 8192) split tokens,
// blocks [8192, 12288) split weights (w = idx>>10).
// ---------------------------------------------------------------------------
__global__ __launch_bounds__(256) void prep_split_kernel(
    const float* __restrict__ X,
    const float* __restrict__ Wq, const float* __restrict__ Wk,
    const float* __restrict__ Wv, const float* __restrict__ Wu)
{
    const int bx = blockIdx.x;
    if (bx < 8192) {
        size_t i = (size_t)bx * 256 + threadIdx.x;
        float4 v = ((const float4*)X)[i];
        float vs[4] = {v.x, v.y, v.z, v.w};
#pragma unroll
        for (int j = 0; j < 4; j++) {
            __nv_bfloat16 hi = __float2bfloat16(vs[j]);
            float lo = vs[j] - __bfloat162float(hi);
            g_x_hi[i * 4 + j] = hi;
            g_x_lo[i * 4 + j] = __float2bfloat16(lo);
        }
    } else {
        const int wx = bx - 8192;
        const int w  = wx >> 10;
        const float* W = (w == 0) ? Wq : (w == 1) ? Wk : (w == 2) ? Wv : Wu;
        size_t i = (size_t)(wx & 1023) * 256 + threadIdx.x;
        float4 v = ((const float4*)W)[i];
        float vs[4] = {v.x, v.y, v.z, v.w};
        size_t base = (size_t)w * DD * DD + i * 4;
#pragma unroll
        for (int j = 0; j < 4; j++) {
            __nv_bfloat16 hi = __float2bfloat16(vs[j]);
            float lo = vs[j] - __bfloat162float(hi);
            g_w_hi[base + j] = hi;
            g_w_lo[base + j] = __float2bfloat16(lo);
        }
    }
}

// ---------------------------------------------------------------------------
// Split-bf16 HMMA GEMM, 3-stage cp.async pipeline; kc-loop unrolled by 3 so
// compute/prefetch buffer indices are compile-time constants.
// mode<3 epilogue staged through smem for coalesced 16B stores.
// ---------------------------------------------------------------------------
#define GK 32
#define SA2 40            // A stride (b16): 32 + 8 pad
#define SB2 136           // B stride (b16)
#define SA_HI_B 0
#define SA_LO_B 10240     // 128*40*2
#define SB_HI_B 20480
#define SB_LO_B 29184
#define STAGE_B 37888
#define NSTAGE 3
#define GEMM_SMEM_BYTES (NSTAGE*STAGE_B)
#define EP_STR 136
#define EP_HI 0
#define EP_LO (128*EP_STR*2)

__global__ __launch_bounds__(256, 2) void gemm_hmma_kernel(
    int mode_base, const float* __restrict__ bias, float* __restrict__ out_ptr)
{
    extern __shared__ __align__(16) char gsm[];
    const uint32_t smem_base = smem_u32(gsm);

    const int t    = threadIdx.x;
    const int lane = t & 31;
    const int wid  = t >> 5;
    const int wm   = wid & 3;
    const int wn   = wid >> 2;
    const int mode = mode_base + blockIdx.z;

    const int n0 = blockIdx.x * 128;
    const int m0 = blockIdx.y * 128;

    const __nv_bfloat16* Ahi = (mode < 3) ? g_x_hi : g_c_hi;
    const __nv_bfloat16* Alo = (mode < 3) ? g_x_lo : g_c_lo;
    const __nv_bfloat16* Bhi = g_w_hi + (size_t)mode * DD * DD;
    const __nv_bfloat16* Blo = g_w_lo + (size_t)mode * DD * DD;

    float acc[2][8][4];
#pragma unroll
    for (int mi = 0; mi < 2; mi++)
#pragma unroll
        for (int nj = 0; nj < 8; nj++)
#pragma unroll
            for (int e = 0; e < 4; e++) acc[mi][nj][e] = 0.f;

    const int lrow = lane & 15;
    const int lcol = (lane >> 4) * 8;

    const int arow0 = t >> 2,          aseg0 = (t & 3) * 8;
    const int arow1 = (t + 256) >> 2,  aseg1 = ((t + 256) & 3) * 8;
    const int brow0 = t >> 4,          bseg0 = (t & 15) * 8;
    const int brow1 = (t + 256) >> 4,  bseg1 = ((t + 256) & 15) * 8;

#define GEMM_PREFETCH(KC, SBUF) do {                                        \
    const int k0_ = (KC) * GK;                                              \
    const uint32_t sb_ = smem_base + (uint32_t)(SBUF) * STAGE_B;            \
    {   size_t go = (size_t)(m0 + arow0) * DD + k0_ + aseg0;                \
        uint32_t so = sb_ + (uint32_t)(arow0 * SA2 + aseg0) * 2;            \
        cp_async16(so + SA_HI_B, Ahi + go);                                 \
        cp_async16(so + SA_LO_B, Alo + go); }                               \
    {   size_t go = (size_t)(m0 + arow1) * DD + k0_ + aseg1;                \
        uint32_t so = sb_ + (uint32_t)(arow1 * SA2 + aseg1) * 2;            \
        cp_async16(so + SA_HI_B, Ahi + go);                                 \
        cp_async16(so + SA_LO_B, Alo + go); }                               \
    {   size_t go = (size_t)(k0_ + brow0) * DD + n0 + bseg0;                \
        uint32_t so = sb_ + (uint32_t)(brow0 * SB2 + bseg0) * 2;            \
        cp_async16(so + SB_HI_B, Bhi + go);                                 \
        cp_async16(so + SB_LO_B, Blo + go); }                               \
    {   size_t go = (size_t)(k0_ + brow1) * DD + n0 + bseg1;                \
        uint32_t so = sb_ + (uint32_t)(brow1 * SB2 + bseg1) * 2;            \
        cp_async16(so + SB_HI_B, Bhi + go);                                 \
        cp_async16(so + SB_LO_B, Blo + go); }                               \
    CP_COMMIT; } while (0)

#define GEMM_STEP(KC, CBUF, PBUF) do {                                      \
    if ((KC) <= 29) { CP_WAIT1; } else { CP_WAIT0; }                        \
    __syncthreads();                                                        \
    if ((KC) + 2 < 32) { GEMM_PREFETCH((KC) + 2, PBUF); }                   \
    const uint32_t sb = smem_base + (uint32_t)(CBUF) * STAGE_B;             \
    _Pragma("unroll")                                                       \
    for (int kk = 0; kk < 2; kk++) {                                        \
        uint32_t ah[2][4], al[2][4];                                        \
        _Pragma("unroll")                                                   \
        for (int mi = 0; mi < 2; mi++) {                                    \
            uint32_t off = (uint32_t)((wm * 32 + mi * 16 + lrow) * SA2      \
                           + kk * 16 + lcol) * 2;                           \
            ldsm_x4(ah[mi], sb + SA_HI_B + off);                            \
            ldsm_x4(al[mi], sb + SA_LO_B + off);                            \
        }                                                                   \
        uint32_t bh[8][2], bl[8][2];                                        \
        _Pragma("unroll")                                                   \
        for (int nj = 0; nj < 8; nj++) {                                    \
            uint32_t off = (uint32_t)((kk * 16 + lrow) * SB2                \
                           + wn * 64 + nj * 8) * 2;                         \
            ldsm_x2_trans(bh[nj], sb + SB_HI_B + off);                      \
            ldsm_x2_trans(bl[nj], sb + SB_LO_B + off);                      \
        }                                                                   \
        _Pragma("unroll")                                                   \
        for (int mi = 0; mi < 2; mi++)                                      \
            _Pragma("unroll")                                               \
            for (int nj = 0; nj < 8; nj++) {                                \
                mma_bf16(acc[mi][nj], ah[mi], bh[nj][0], bh[nj][1]);        \
                mma_bf16(acc[mi][nj], ah[mi], bl[nj][0], bl[nj][1]);        \
                mma_bf16(acc[mi][nj], al[mi], bh[nj][0], bh[nj][1]);        \
            }                                                               \
    } } while (0)

    GEMM_PREFETCH(0, 0);
    GEMM_PREFETCH(1, 1);

    // kc = kcb + j; buffer(kc) = j (kcb % 3 == 0), prefetch buffer = (j+2)%3
    for (int kcb = 0; kcb < 30; kcb += 3) {
        GEMM_STEP(kcb + 0, 0, 2);
        GEMM_STEP(kcb + 1, 1, 0);
        GEMM_STEP(kcb + 2, 2, 1);
    }
    GEMM_STEP(30, 0, 2);
    GEMM_STEP(31, 1, 0);

    if (mode < 3) {
        __syncthreads();
#pragma unroll
        for (int mi = 0; mi < 2; mi++) {
            const int rl0 = wm * 32 + mi * 16 + (lane >> 2);
#pragma unroll
            for (int nj = 0; nj < 8; nj++) {
                const int cl = wn * 64 + nj * 8 + (lane & 3) * 2;
#pragma unroll
                for (int half = 0; half < 2; half++) {
                    const int rl = rl0 + half * 8;
                    uint32_t lo, hi = pack_hilo(acc[mi][nj][half * 2 + 0],
                                                acc[mi][nj][half * 2 + 1], lo);
                    uint32_t off = (uint32_t)(rl * EP_STR + cl) * 2;
                    *(uint32_t*)(gsm + EP_HI + off) = hi;
                    *(uint32_t*)(gsm + EP_LO + off) = lo;
                }
            }
        }
        __syncthreads();

        __nv_bfloat16* Oh = (mode == 0) ? g_qh : (mode == 1) ? g_kh : g_vh;
        __nv_bfloat16* Ol = (mode == 0) ? g_ql : (mode == 1) ? g_kl : g_vl;
        for (int i = t; i < 2048; i += 256) {
            const int row = i >> 4;
            const int col = (i & 15) * 8;
            const int r   = m0 + row;
            const int b_  = r >> 12, s = r & 4095;
            const int h   = (n0 + col) >> 6;
            const int dd  = col & 63;
            size_t gidx = (((size_t)(b_ * HH + h)) * SS + s) * HDIM + dd;
            uint32_t soff = (uint32_t)(row * EP_STR + col) * 2;
            *(uint4*)(Oh + gidx) = *(const uint4*)(gsm + EP_HI + soff);
            *(uint4*)(Ol + gidx) = *(const uint4*)(gsm + EP_LO + soff);
        }
    } else {
#pragma unroll
        for (int mi = 0; mi < 2; mi++) {
            const int r0 = m0 + wm * 32 + mi * 16 + (lane >> 2);
#pragma unroll
            for (int nj = 0; nj < 8; nj++) {
                const int col = wn * 64 + nj * 8 + (lane & 3) * 2;
                float bv0 = bias[n0 + col], bv1 = bias[n0 + col + 1];
                float2 st0; st0.x = acc[mi][nj][0] + bv0; st0.y = acc[mi][nj][1] + bv1;
                float2 st1; st1.x = acc[mi][nj][2] + bv0; st1.y = acc[mi][nj][3] + bv1;
                *(float2*)(out_ptr + (size_t)r0 * DD + n0 + col) = st0;
                *(float2*)(out_ptr + (size_t)(r0 + 8) * DD + n0 + col) = st1;
            }
        }
    }
}

// ---------------------------------------------------------------------------
// BigBird sparse attention (R14-proven: heavy CTAs first, cp.async pipelined)
// ---------------------------------------------------------------------------
#define ATT_STRB 144
#define KSTAGE(s) ((s) * 18432)
#define T_VH 36864
#define T_VL 46080
#define T_PEN2 55296
#define T_PEN1 72704
#define ATTN_SMEM_BYTES 72976

__global__ __launch_bounds__(128, 3) void attn_kernel(
    const float* __restrict__ band_mask,
    const float* __restrict__ from_mask,
    const float* __restrict__ to_mask)
{
    extern __shared__ __align__(16) char smraw[];
    const uint32_t smem_base = smem_u32(smraw);
    const float* pen2f = (const float*)(smraw + T_PEN2);
    const float* pen1f = (const float*)(smraw + T_PEN1);

    const int bx = blockIdx.x;
    const int h  = blockIdx.y;
    const int b  = blockIdx.z;
    const int t  = threadIdx.x;
    const int lane = t & 31;
    const int wid  = t >> 5;

    const bool heavy = (bx < 16);
    int qb, ch = 0;
    if (heavy) { qb = bx >> 3; ch = bx & 7; }
    else qb = bx - 14;

    const float rs  = 0.125f;
    const float pen = -10000.f;
    const size_t bh64 = ((size_t)(b * HH + h)) * SS * HDIM;

    {
        const __nv_bfloat16* qhp = g_qh + bh64 + (size_t)qb * BLKSZ * HDIM;
        const __nv_bfloat16* qlp = g_ql + bh64 + (size_t)qb * BLKSZ * HDIM;
        for (int i = t; i < 512; i += 128) {
            int row = i >> 3, seg = (i & 7) * 8;
            *(uint4*)(smraw + row * ATT_STRB + seg * 2)        = *(const uint4*)(qhp + row * HDIM + seg);
            *(uint4*)(smraw + 9216 + row * ATT_STRB + seg * 2) = *(const uint4*)(qlp + row * HDIM + seg);
        }
    }
    __syncthreads();

    uint32_t qfh[4][4], qfl[4][4];
    {
        const int lrow = lane & 15;
        const int lcol = (lane >> 4) * 8;
#pragma unroll
        for (int kk = 0; kk < 4; kk++) {
            uint32_t off = (uint32_t)((wid * 16 + lrow) * ATT_STRB + (kk * 16 + lcol) * 2);
            ldsm_x4(qfh[kk], smem_base + off);
            ldsm_x4(qfl[kk], smem_base + 9216 + off);
        }
    }
    __syncthreads();

    int nt;
    int kbs[5];
    bool is_band = false;
    if (heavy) {
        nt = 8;
    } else if (qb == NGB) {
        nt = 5; kbs[0]=0; kbs[1]=1; kbs[2]=2; kbs[3]=3; kbs[4]=4;
    } else if (qb == NB - 1) {
        nt = 5; kbs[0]=0; kbs[1]=1; kbs[2]=61; kbs[3]=62; kbs[4]=63;
    } else {
        nt = 5; kbs[0]=0; kbs[1]=1; kbs[2]=qb-1; kbs[3]=qb; kbs[4]=qb+1; is_band = true;
    }

#define KB_OF(IT) (heavy ? (ch * 8 + (IT)) : kbs[(IT)])

#define ISSUE_K(KB, STG) do {                                               \
    const __nv_bfloat16* khp_ = g_kh + bh64 + (size_t)(KB) * BLKSZ * HDIM;  \
    const __nv_bfloat16* klp_ = g_kl + bh64 + (size_t)(KB) * BLKSZ * HDIM;  \
    for (int i = t; i < 512; i += 128) {                                    \
        int row = i >> 3, seg = (i & 7) * 8;                                \
        uint32_t so = smem_base + KSTAGE(STG) + row * ATT_STRB + seg * 2;   \
        cp_async16(so,        khp_ + row * HDIM + seg);                     \
        cp_async16(so + 9216, klp_ + row * HDIM + seg);                     \
    }                                                                       \
    CP_COMMIT; } while (0)

#define ISSUE_VP(IT, KB, BANDT) do {                                        \
    const __nv_bfloat16* vhp_ = g_vh + bh64 + (size_t)(KB) * BLKSZ * HDIM;  \
    const __nv_bfloat16* vlp_ = g_vl + bh64 + (size_t)(KB) * BLKSZ * HDIM;  \
    for (int i = t; i < 512; i += 128) {                                    \
        int row = i >> 3, seg = (i & 7) * 8;                                \
        uint32_t so = smem_base + T_VH + row * ATT_STRB + seg * 2;          \
        cp_async16(so,        vhp_ + row * HDIM + seg);                     \
        cp_async16(so + 9216, vlp_ + row * HDIM + seg);                     \
    }                                                                       \
    if (BANDT) {                                                            \
        const float* bmb_ = band_mask                                       \
            + ((size_t)(b * 60 + (qb - 3)) * 64) * 192 + (size_t)((IT) - 2) * 64; \
        for (int i = t; i < 1024; i += 128) {                               \
            int row = i >> 4, c = i & 15;                                   \
            cp_async16(smem_base + T_PEN2 + row * 272 + c * 16,             \
                       bmb_ + row * 192 + c * 4);                           \
        }                                                                   \
    } else if (t < 16) {                                                    \
        cp_async16(smem_base + T_PEN1 + t * 16,                             \
                   to_mask + (size_t)b * SS + (KB) * BLKSZ + t * 4);        \
    }                                                                       \
    CP_COMMIT; } while (0)

    float m0 = -1e30f, m1 = -1e30f, l0 = 0.f, l1 = 0.f;
    float o[8][4];
#pragma unroll
    for (int nj = 0; nj < 8; nj++)
#pragma unroll
        for (int e = 0; e < 4; e++) o[nj][e] = 0.f;

    ISSUE_K(KB_OF(0), 0);

    for (int it = 0; it < nt; it++) {
        const int kb = KB_OF(it);
        const bool band_tile = (is_band && it >= 2);

        ISSUE_VP(it, kb, band_tile);
        if (it + 1 < nt) {
            ISSUE_K(KB_OF(it + 1), (it + 1) & 1);
            CP_WAIT2;
        } else {
            CP_WAIT1;
        }
        __syncthreads();

        const uint32_t kst = smem_base + KSTAGE(it & 1);
        float acc[8][4];
#pragma unroll
        for (int nj = 0; nj < 8; nj++)
#pragma unroll
            for (int e = 0; e < 4; e++) acc[nj][e] = 0.f;

#pragma unroll
        for (int nj = 0; nj < 8; nj++) {
            uint32_t kh8[8], kl8[8];
            uint32_t rbase = (uint32_t)((nj * 8 + (lane & 7)) * ATT_STRB + (lane >> 3) * 16);
            ldsm_x4(kh8,     kst + rbase);
            ldsm_x4(kh8 + 4, kst + rbase + 64);
            ldsm_x4(kl8,     kst + 9216 + rbase);
            ldsm_x4(kl8 + 4, kst + 9216 + rbase + 64);
#pragma unroll
            for (int kk = 0; kk < 4; kk++) {
                mma_bf16(acc[nj], qfh[kk], kh8[2*kk], kh8[2*kk+1]);
                mma_bf16(acc[nj], qfh[kk], kl8[2*kk], kl8[2*kk+1]);
                mma_bf16(acc[nj], qfl[kk], kh8[2*kk], kh8[2*kk+1]);
            }
        }

        if (it + 1 < nt) { CP_WAIT1; } else { CP_WAIT0; }
        __syncthreads();

        const int qr0 = wid * 16 + (lane >> 2);
#pragma unroll
        for (int nj = 0; nj < 8; nj++) {
#pragma unroll
            for (int e = 0; e < 4; e++) {
                int col = nj * 8 + (lane & 3) * 2 + (e & 1);
                float mv = band_tile
                    ? pen2f[(qr0 + (e >> 1) * 8) * 68 + col]
                    : pen1f[col];
                acc[nj][e] = acc[nj][e] * rs + (1.f - mv) * pen;
            }
        }

        float tm0 = -1e30f, tm1 = -1e30f;
#pragma unroll
        for (int nj = 0; nj < 8; nj++) {
            tm0 = fmaxf(tm0, fmaxf(acc[nj][0], acc[nj][1]));
            tm1 = fmaxf(tm1, fmaxf(acc[nj][2], acc[nj][3]));
        }
        tm0 = fmaxf(tm0, __shfl_xor_sync(0xffffffffu, tm0, 1));
        tm0 = fmaxf(tm0, __shfl_xor_sync(0xffffffffu, tm0, 2));
        tm1 = fmaxf(tm1, __shfl_xor_sync(0xffffffffu, tm1, 1));
        tm1 = fmaxf(tm1, __shfl_xor_sync(0xffffffffu, tm1, 2));

        float nm0 = fmaxf(m0, tm0), nm1 = fmaxf(m1, tm1);
        float c0 = __expf(m0 - nm0), c1 = __expf(m1 - nm1);
        float ts0 = 0.f, ts1 = 0.f;
#pragma unroll
        for (int nj = 0; nj < 8; nj++) {
            acc[nj][0] = __expf(acc[nj][0] - nm0);
            acc[nj][1] = __expf(acc[nj][1] - nm0);
            acc[nj][2] = __expf(acc[nj][2] - nm1);
            acc[nj][3] = __expf(acc[nj][3] - nm1);
            ts0 += acc[nj][0] + acc[nj][1];
            ts1 += acc[nj][2] + acc[nj][3];
        }
        ts0 += __shfl_xor_sync(0xffffffffu, ts0, 1);
        ts0 += __shfl_xor_sync(0xffffffffu, ts0, 2);
        ts1 += __shfl_xor_sync(0xffffffffu, ts1, 1);
        ts1 += __shfl_xor_sync(0xffffffffu, ts1, 2);
        l0 = l0 * c0 + ts0;  l1 = l1 * c1 + ts1;
        m0 = nm0;  m1 = nm1;
#pragma unroll
        for (int nj = 0; nj < 8; nj++) {
            o[nj][0] *= c0; o[nj][1] *= c0;
            o[nj][2] *= c1; o[nj][3] *= c1;
        }

        uint32_t phi[4][4], plo[4][4];
#pragma unroll
        for (int kk2 = 0; kk2 < 4; kk2++) {
            phi[kk2][0] = pack_hilo(acc[2*kk2][0],   acc[2*kk2][1],   plo[kk2][0]);
            phi[kk2][1] = pack_hilo(acc[2*kk2][2],   acc[2*kk2][3],   plo[kk2][1]);
            phi[kk2][2] = pack_hilo(acc[2*kk2+1][0], acc[2*kk2+1][1], plo[kk2][2]);
            phi[kk2][3] = pack_hilo(acc[2*kk2+1][2], acc[2*kk2+1][3], plo[kk2][3]);
        }

#pragma unroll
        for (int njd = 0; njd < 8; njd++) {
#pragma unroll
            for (int kk2 = 0; kk2 < 4; kk2++) {
                uint32_t vh[2], vl[2];
                uint32_t off = (uint32_t)((kk2 * 16 + (lane & 15)) * ATT_STRB + njd * 16);
                ldsm_x2_trans(vh, smem_base + T_VH + off);
                ldsm_x2_trans(vl, smem_base + T_VL + off);
                mma_bf16(o[njd], phi[kk2], vh[0], vh[1]);
                mma_bf16(o[njd], phi[kk2], vl[0], vl[1]);
                mma_bf16(o[njd], plo[kk2], vh[0], vh[1]);
            }
        }
        __syncthreads();
    }

    const int r0 = wid * 16 + (lane >> 2);
    if (!heavy) {
        const int s0 = qb * BLKSZ + r0;
        const int s1 = s0 + 8;
        float inv0 = from_mask[(size_t)b * SS + s0] / l0;
        float inv1 = from_mask[(size_t)b * SS + s1] / l1;
#pragma unroll
        for (int njd = 0; njd < 8; njd++) {
            const int col = njd * 8 + (lane & 3) * 2;
            {
                size_t idx = ((size_t)b * SS + s0) * DD + h * HDIM + col;
                uint32_t lo, hi = pack_hilo(o[njd][0] * inv0, o[njd][1] * inv0, lo);
                *(uint32_t*)(g_c_hi + idx) = hi;
                *(uint32_t*)(g_c_lo + idx) = lo;
            }
            {
                size_t idx = ((size_t)b * SS + s1) * DD + h * HDIM + col;
                uint32_t lo, hi = pack_hilo(o[njd][2] * inv1, o[njd][3] * inv1, lo);
                *(uint32_t*)(g_c_hi + idx) = hi;
                *(uint32_t*)(g_c_lo + idx) = lo;
            }
        }
    } else {
        const int cid = ((b * HH + h) * 2 + qb) * 8 + ch;
        float* pob = g_po + (size_t)cid * 4096;
#pragma unroll
        for (int njd = 0; njd < 8; njd++) {
            const int col = njd * 8 + (lane & 3) * 2;
            float2 s0v; s0v.x = o[njd][0]; s0v.y = o[njd][1];
            float2 s1v; s1v.x = o[njd][2]; s1v.y = o[njd][3];
            *(float2*)(pob + r0 * 64 + col) = s0v;
            *(float2*)(pob + (r0 + 8) * 64 + col) = s1v;
        }
        if ((lane & 3) == 0) {
            g_pm[cid * 64 + r0]     = m0;
            g_pm[cid * 64 + r0 + 8] = m1;
            g_pl[cid * 64 + r0]     = l0;
            g_pl[cid * 64 + r0 + 8] = l1;
        }
    }
}

// ---------------------------------------------------------------------------
// Combine split-KV partials for heavy q-blocks.
// ---------------------------------------------------------------------------
__global__ __launch_bounds__(128) void attn_combine(const float* __restrict__ from_mask)
{
    const int x  = blockIdx.x;
    const int qb = x & 1;
    const int h  = (x >> 1) & 15;
    const int b  = x >> 5;
    const int t  = threadIdx.x;
    const int r  = t >> 1;
    const int c0 = (t & 1) * 32;
    const int base8 = x * 8;

    float m[8], l[8], M = -1e30f;
#pragma unroll
    for (int i = 0; i < 8; i++) {
        m[i] = g_pm[(base8 + i) * 64 + r];
        l[i] = g_pl[(base8 + i) * 64 + r];
        M = fmaxf(M, m[i]);
    }
    float L = 0.f, sc[8];
#pragma unroll
    for (int i = 0; i < 8; i++) { sc[i] = __expf(m[i] - M); L += l[i] * sc[i]; }

    float acc[32];
#pragma unroll
    for (int c = 0; c < 32; c++) acc[c] = 0.f;
#pragma unroll
    for (int i = 0; i < 8; i++) {
        const float* p = g_po + (size_t)(base8 + i) * 4096 + r * 64 + c0;
        float s = sc[i];
#pragma unroll
        for (int c4 = 0; c4 < 8; c4++) {
            float4 v = *(const float4*)(p + c4 * 4);
            acc[c4*4+0] += s * v.x; acc[c4*4+1] += s * v.y;
            acc[c4*4+2] += s * v.z; acc[c4*4+3] += s * v.w;
        }
    }

    const int s_ = qb * BLKSZ + r;
    float inv = from_mask[(size_t)b * SS + s_] / L;
    size_t idx = ((size_t)b * SS + s_) * DD + h * HDIM + c0;
#pragma unroll
    for (int c = 0; c < 32; c += 2) {
        uint32_t lo, hi = pack_hilo(acc[c] * inv, acc[c+1] * inv, lo);
        *(uint32_t*)(g_c_hi + idx + c) = hi;
        *(uint32_t*)(g_c_lo + idx + c) = lo;
    }
}

// ---------------------------------------------------------------------------
extern "C" void kernel_launch(void* const* d_in, const int* in_sizes, int n_in,
                              void* d_out, int out_size)
{
    const float* tokens    = (const float*)d_in[0];
    const float* band_mask = (const float*)d_in[1];
    const float* from_mask = (const float*)d_in[2];
    const float* to_mask   = (const float*)d_in[3];
    const float* Wq        = (const float*)d_in[4];
    const float* Wk        = (const float*)d_in[5];
    const float* Wv        = (const float*)d_in[6];
    const float* Wu        = (const float*)d_in[7];
    const float* bu        = (const float*)d_in[8];
    float* out = (float*)d_out;

    cudaFuncSetAttribute(attn_kernel,
                         cudaFuncAttributeMaxDynamicSharedMemorySize, ATTN_SMEM_BYTES);
    cudaFuncSetAttribute(gemm_hmma_kernel,
                         cudaFuncAttributeMaxDynamicSharedMemorySize, GEMM_SMEM_BYTES);

    // 0) Fused precision-split of tokens + all four weights
    prep_split_kernel<<<12288, 256>>>(tokens, Wq, Wk, Wv, Wu);

    // 1) QKV projections (3-stage pipelined HMMA, const-buffer unrolled)
    gemm_hmma_kernel<<<dim3(8, 64, 3), 256, GEMM_SMEM_BYTES>>>(0, nullptr, nullptr);

    // 2) Sparse attention (heavy CTAs first in grid order)
    attn_kernel<<<dim3(78, HH, BB), 128, ATTN_SMEM_BYTES>>>(band_mask, from_mask, to_mask);

    // 2b) Combine heavy partials
    attn_combine<<<64, 128>>>(from_mask);

    // 3) Output projection + bias (3-stage pipelined HMMA)
    gemm_hmma_kernel<<<dim3(8, 64, 1), 256, GEMM_SMEM_BYTES>>>(3, bu, out);
}

// round 16
// speedup vs baseline: 1.9060x; 1.0158x over previous
#include <cuda_runtime.h>
#include <cuda_bf16.h>
#include <cstdint>
#include <math.h>

#define BB 2
#define SS 4096
#define DD 1024
#define HH 16
#define BLKSZ 64
#define NB 64          // S / BLK
#define NGB 2          // G / BLK
#define HDIM 64        // D / H
#define MROWS (BB*SS)  // 8192

// ---------------------------------------------------------------------------
// Device scratch (no allocation allowed)
// ---------------------------------------------------------------------------
__device__ __nv_bfloat16 g_x_hi[(size_t)MROWS*DD];
__device__ __nv_bfloat16 g_x_lo[(size_t)MROWS*DD];
__device__ __nv_bfloat16 g_c_hi[(size_t)MROWS*DD];
__device__ __nv_bfloat16 g_c_lo[(size_t)MROWS*DD];
__device__ __nv_bfloat16 g_w_hi[(size_t)4*DD*DD];   // [w][k][n] (native layout)
__device__ __nv_bfloat16 g_w_lo[(size_t)4*DD*DD];
// Q/K/V head-split bf16 hi/lo: [b,h,s,64]
__device__ __nv_bfloat16 g_qh[(size_t)BB*HH*SS*HDIM];
__device__ __nv_bfloat16 g_ql[(size_t)BB*HH*SS*HDIM];
__device__ __nv_bfloat16 g_kh[(size_t)BB*HH*SS*HDIM];
__device__ __nv_bfloat16 g_kl[(size_t)BB*HH*SS*HDIM];
__device__ __nv_bfloat16 g_vh[(size_t)BB*HH*SS*HDIM];
__device__ __nv_bfloat16 g_vl[(size_t)BB*HH*SS*HDIM];
// split-KV partials for heavy q-blocks
__device__ float g_po[(size_t)512*4096];
__device__ float g_pm[512*64];
__device__ float g_pl[512*64];

// ---------------------------------------------------------------------------
// mma.sync / ldmatrix / cp.async helpers (generic sm_80+ PTX)
// ---------------------------------------------------------------------------
__device__ __forceinline__ uint32_t smem_u32(const void* p) {
    uint32_t a;
    asm("{ .reg .u64 t; cvta.to.shared.u64 t, %1; cvt.u32.u64 %0, t; }" : "=r"(a) : "l"(p));
    return a;
}
__device__ __forceinline__ void ldsm_x4(uint32_t* r, uint32_t addr) {
    asm volatile("ldmatrix.sync.aligned.m8n8.x4.shared.b16 {%0,%1,%2,%3}, [%4];"
        : "=r"(r[0]), "=r"(r[1]), "=r"(r[2]), "=r"(r[3]) : "r"(addr));
}
__device__ __forceinline__ void ldsm_x2_trans(uint32_t* r, uint32_t addr) {
    asm volatile("ldmatrix.sync.aligned.m8n8.x2.trans.shared.b16 {%0,%1}, [%2];"
        : "=r"(r[0]), "=r"(r[1]) : "r"(addr));
}
__device__ __forceinline__ void mma_bf16(float (&c)[4], const uint32_t* a,
                                         uint32_t b0, uint32_t b1) {
    asm volatile("mma.sync.aligned.m16n8k16.row.col.f32.bf16.bf16.f32 "
        "{%0,%1,%2,%3}, {%4,%5,%6,%7}, {%8,%9}, {%0,%1,%2,%3};"
        : "+f"(c[0]), "+f"(c[1]), "+f"(c[2]), "+f"(c[3])
        : "r"(a[0]), "r"(a[1]), "r"(a[2]), "r"(a[3]), "r"(b0), "r"(b1));
}
__device__ __forceinline__ void cp_async16(uint32_t saddr, const void* gptr) {
    asm volatile("cp.async.cg.shared.global [%0], [%1], 16;" :: "r"(saddr), "l"(gptr));
}
#define CP_COMMIT asm volatile("cp.async.commit_group;")
#define CP_WAIT2  asm volatile("cp.async.wait_group 2;")
#define CP_WAIT1  asm volatile("cp.async.wait_group 1;")
#define CP_WAIT0  asm volatile("cp.async.wait_group 0;")

// pack two floats -> bf16x2 hi, bf16x2 lo (residual)
__device__ __forceinline__ uint32_t pack_hilo(float a, float b, uint32_t& lo_out) {
    __nv_bfloat162 h; h.x = __float2bfloat16(a); h.y = __float2bfloat16(b);
    __nv_bfloat162 l;
    l.x = __float2bfloat16(a - __bfloat162float(h.x));
    l.y = __float2bfloat16(b - __bfloat162float(h.y));
    lo_out = *(uint32_t*)&l;
    return *(uint32_t*)&h;
}

// ---------------------------------------------------------------------------
// Fused precision-split prep: blocks [0, 8192) split tokens,
// blocks [8192, 12288) split weights (w = idx>>10).
// ---------------------------------------------------------------------------
__global__ __launch_bounds__(256) void prep_split_kernel(
    const float* __restrict__ X,
    const float* __restrict__ Wq, const float* __restrict__ Wk,
    const float* __restrict__ Wv, const float* __restrict__ Wu)
{
    const int bx = blockIdx.x;
    if (bx < 8192) {
        size_t i = (size_t)bx * 256 + threadIdx.x;
        float4 v = ((const float4*)X)[i];
        float vs[4] = {v.x, v.y, v.z, v.w};
#pragma unroll
        for (int j = 0; j < 4; j++) {
            __nv_bfloat16 hi = __float2bfloat16(vs[j]);
            float lo = vs[j] - __bfloat162float(hi);
            g_x_hi[i * 4 + j] = hi;
            g_x_lo[i * 4 + j] = __float2bfloat16(lo);
        }
    } else {
        const int wx = bx - 8192;
        const int w  = wx >> 10;
        const float* W = (w == 0) ? Wq : (w == 1) ? Wk : (w == 2) ? Wv : Wu;
        size_t i = (size_t)(wx & 1023) * 256 + threadIdx.x;
        float4 v = ((const float4*)W)[i];
        float vs[4] = {v.x, v.y, v.z, v.w};
        size_t base = (size_t)w * DD * DD + i * 4;
#pragma unroll
        for (int j = 0; j < 4; j++) {
            __nv_bfloat16 hi = __float2bfloat16(vs[j]);
            float lo = vs[j] - __bfloat162float(hi);
            g_w_hi[base + j] = hi;
            g_w_lo[base + j] = __float2bfloat16(lo);
        }
    }
}

// ---------------------------------------------------------------------------
// Split-bf16 HMMA GEMM, 3-stage cp.async pipeline; kc-loop unrolled by 3 so
// compute/prefetch buffer indices are compile-time constants.
// mode<3 epilogue staged through smem for coalesced 16B stores.
// ---------------------------------------------------------------------------
#define GK 32
#define SA2 40            // A stride (b16): 32 + 8 pad
#define SB2 136           // B stride (b16)
#define SA_HI_B 0
#define SA_LO_B 10240     // 128*40*2
#define SB_HI_B 20480
#define SB_LO_B 29184
#define STAGE_B 37888
#define NSTAGE 3
#define GEMM_SMEM_BYTES (NSTAGE*STAGE_B)
#define EP_STR 136
#define EP_HI 0
#define EP_LO (128*EP_STR*2)

__global__ __launch_bounds__(256, 2) void gemm_hmma_kernel(
    int mode_base, const float* __restrict__ bias, float* __restrict__ out_ptr)
{
    extern __shared__ __align__(16) char gsm[];
    const uint32_t smem_base = smem_u32(gsm);

    const int t    = threadIdx.x;
    const int lane = t & 31;
    const int wid  = t >> 5;
    const int wm   = wid & 3;
    const int wn   = wid >> 2;
    const int mode = mode_base + blockIdx.z;

    const int n0 = blockIdx.x * 128;
    const int m0 = blockIdx.y * 128;

    const __nv_bfloat16* Ahi = (mode < 3) ? g_x_hi : g_c_hi;
    const __nv_bfloat16* Alo = (mode < 3) ? g_x_lo : g_c_lo;
    const __nv_bfloat16* Bhi = g_w_hi + (size_t)mode * DD * DD;
    const __nv_bfloat16* Blo = g_w_lo + (size_t)mode * DD * DD;

    float acc[2][8][4];
#pragma unroll
    for (int mi = 0; mi < 2; mi++)
#pragma unroll
        for (int nj = 0; nj < 8; nj++)
#pragma unroll
            for (int e = 0; e < 4; e++) acc[mi][nj][e] = 0.f;

    const int lrow = lane & 15;
    const int lcol = (lane >> 4) * 8;

    const int arow0 = t >> 2,          aseg0 = (t & 3) * 8;
    const int arow1 = (t + 256) >> 2,  aseg1 = ((t + 256) & 3) * 8;
    const int brow0 = t >> 4,          bseg0 = (t & 15) * 8;
    const int brow1 = (t + 256) >> 4,  bseg1 = ((t + 256) & 15) * 8;

#define GEMM_PREFETCH(KC, SBUF) do {                                        \
    const int k0_ = (KC) * GK;                                              \
    const uint32_t sb_ = smem_base + (uint32_t)(SBUF) * STAGE_B;            \
    {   size_t go = (size_t)(m0 + arow0) * DD + k0_ + aseg0;                \
        uint32_t so = sb_ + (uint32_t)(arow0 * SA2 + aseg0) * 2;            \
        cp_async16(so + SA_HI_B, Ahi + go);                                 \
        cp_async16(so + SA_LO_B, Alo + go); }                               \
    {   size_t go = (size_t)(m0 + arow1) * DD + k0_ + aseg1;                \
        uint32_t so = sb_ + (uint32_t)(arow1 * SA2 + aseg1) * 2;            \
        cp_async16(so + SA_HI_B, Ahi + go);                                 \
        cp_async16(so + SA_LO_B, Alo + go); }                               \
    {   size_t go = (size_t)(k0_ + brow0) * DD + n0 + bseg0;                \
        uint32_t so = sb_ + (uint32_t)(brow0 * SB2 + bseg0) * 2;            \
        cp_async16(so + SB_HI_B, Bhi + go);                                 \
        cp_async16(so + SB_LO_B, Blo + go); }                               \
    {   size_t go = (size_t)(k0_ + brow1) * DD + n0 + bseg1;                \
        uint32_t so = sb_ + (uint32_t)(brow1 * SB2 + bseg1) * 2;            \
        cp_async16(so + SB_HI_B, Bhi + go);                                 \
        cp_async16(so + SB_LO_B, Blo + go); }                               \
    CP_COMMIT; } while (0)

#define GEMM_STEP(KC, CBUF, PBUF) do {                                      \
    if ((KC) <= 29) { CP_WAIT1; } else { CP_WAIT0; }                        \
    __syncthreads();                                                        \
    if ((KC) + 2 < 32) { GEMM_PREFETCH((KC) + 2, PBUF); }                   \
    const uint32_t sb = smem_base + (uint32_t)(CBUF) * STAGE_B;             \
    _Pragma("unroll")                                                       \
    for (int kk = 0; kk < 2; kk++) {                                        \
        uint32_t ah[2][4], al[2][4];                                        \
        _Pragma("unroll")                                                   \
        for (int mi = 0; mi < 2; mi++) {                                    \
            uint32_t off = (uint32_t)((wm * 32 + mi * 16 + lrow) * SA2      \
                           + kk * 16 + lcol) * 2;                           \
            ldsm_x4(ah[mi], sb + SA_HI_B + off);                            \
            ldsm_x4(al[mi], sb + SA_LO_B + off);                            \
        }                                                                   \
        uint32_t bh[8][2], bl[8][2];                                        \
        _Pragma("unroll")                                                   \
        for (int nj = 0; nj < 8; nj++) {                                    \
            uint32_t off = (uint32_t)((kk * 16 + lrow) * SB2                \
                           + wn * 64 + nj * 8) * 2;                         \
            ldsm_x2_trans(bh[nj], sb + SB_HI_B + off);                      \
            ldsm_x2_trans(bl[nj], sb + SB_LO_B + off);                      \
        }                                                                   \
        _Pragma("unroll")                                                   \
        for (int mi = 0; mi < 2; mi++)                                      \
            _Pragma("unroll")                                               \
            for (int nj = 0; nj < 8; nj++) {                                \
                mma_bf16(acc[mi][nj], ah[mi], bh[nj][0], bh[nj][1]);        \
                mma_bf16(acc[mi][nj], ah[mi], bl[nj][0], bl[nj][1]);        \
                mma_bf16(acc[mi][nj], al[mi], bh[nj][0], bh[nj][1]);        \
            }                                                               \
    } } while (0)

    GEMM_PREFETCH(0, 0);
    GEMM_PREFETCH(1, 1);

    for (int kcb = 0; kcb < 30; kcb += 3) {
        GEMM_STEP(kcb + 0, 0, 2);
        GEMM_STEP(kcb + 1, 1, 0);
        GEMM_STEP(kcb + 2, 2, 1);
    }
    GEMM_STEP(30, 0, 2);
    GEMM_STEP(31, 1, 0);

    if (mode < 3) {
        __syncthreads();
#pragma unroll
        for (int mi = 0; mi < 2; mi++) {
            const int rl0 = wm * 32 + mi * 16 + (lane >> 2);
#pragma unroll
            for (int nj = 0; nj < 8; nj++) {
                const int cl = wn * 64 + nj * 8 + (lane & 3) * 2;
#pragma unroll
                for (int half = 0; half < 2; half++) {
                    const int rl = rl0 + half * 8;
                    uint32_t lo, hi = pack_hilo(acc[mi][nj][half * 2 + 0],
                                                acc[mi][nj][half * 2 + 1], lo);
                    uint32_t off = (uint32_t)(rl * EP_STR + cl) * 2;
                    *(uint32_t*)(gsm + EP_HI + off) = hi;
                    *(uint32_t*)(gsm + EP_LO + off) = lo;
                }
            }
        }
        __syncthreads();

        __nv_bfloat16* Oh = (mode == 0) ? g_qh : (mode == 1) ? g_kh : g_vh;
        __nv_bfloat16* Ol = (mode == 0) ? g_ql : (mode == 1) ? g_kl : g_vl;
        for (int i = t; i < 2048; i += 256) {
            const int row = i >> 4;
            const int col = (i & 15) * 8;
            const int r   = m0 + row;
            const int b_  = r >> 12, s = r & 4095;
            const int h   = (n0 + col) >> 6;
            const int dd  = col & 63;
            size_t gidx = (((size_t)(b_ * HH + h)) * SS + s) * HDIM + dd;
            uint32_t soff = (uint32_t)(row * EP_STR + col) * 2;
            *(uint4*)(Oh + gidx) = *(const uint4*)(gsm + EP_HI + soff);
            *(uint4*)(Ol + gidx) = *(const uint4*)(gsm + EP_LO + soff);
        }
    } else {
#pragma unroll
        for (int mi = 0; mi < 2; mi++) {
            const int r0 = m0 + wm * 32 + mi * 16 + (lane >> 2);
#pragma unroll
            for (int nj = 0; nj < 8; nj++) {
                const int col = wn * 64 + nj * 8 + (lane & 3) * 2;
                float bv0 = bias[n0 + col], bv1 = bias[n0 + col + 1];
                float2 st0; st0.x = acc[mi][nj][0] + bv0; st0.y = acc[mi][nj][1] + bv1;
                float2 st1; st1.x = acc[mi][nj][2] + bv0; st1.y = acc[mi][nj][3] + bv1;
                *(float2*)(out_ptr + (size_t)r0 * DD + n0 + col) = st0;
                *(float2*)(out_ptr + (size_t)(r0 + 8) * DD + n0 + col) = st1;
            }
        }
    }
}

// ---------------------------------------------------------------------------
// BigBird sparse attention (R15-proven: heavy CTAs first, cp.async pipelined)
// ---------------------------------------------------------------------------
#define ATT_STRB 144
#define KSTAGE(s) ((s) * 18432)
#define T_VH 36864
#define T_VL 46080
#define T_PEN2 55296
#define T_PEN1 72704
#define ATTN_SMEM_BYTES 72976

__global__ __launch_bounds__(128, 3) void attn_kernel(
    const float* __restrict__ band_mask,
    const float* __restrict__ from_mask,
    const float* __restrict__ to_mask)
{
    extern __shared__ __align__(16) char smraw[];
    const uint32_t smem_base = smem_u32(smraw);
    const float* pen2f = (const float*)(smraw + T_PEN2);
    const float* pen1f = (const float*)(smraw + T_PEN1);

    const int bx = blockIdx.x;
    const int h  = blockIdx.y;
    const int b  = blockIdx.z;
    const int t  = threadIdx.x;
    const int lane = t & 31;
    const int wid  = t >> 5;

    const bool heavy = (bx < 16);
    int qb, ch = 0;
    if (heavy) { qb = bx >> 3; ch = bx & 7; }
    else qb = bx - 14;

    const float rs  = 0.125f;
    const float pen = -10000.f;
    const size_t bh64 = ((size_t)(b * HH + h)) * SS * HDIM;

    {
        const __nv_bfloat16* qhp = g_qh + bh64 + (size_t)qb * BLKSZ * HDIM;
        const __nv_bfloat16* qlp = g_ql + bh64 + (size_t)qb * BLKSZ * HDIM;
        for (int i = t; i < 512; i += 128) {
            int row = i >> 3, seg = (i & 7) * 8;
            *(uint4*)(smraw + row * ATT_STRB + seg * 2)        = *(const uint4*)(qhp + row * HDIM + seg);
            *(uint4*)(smraw + 9216 + row * ATT_STRB + seg * 2) = *(const uint4*)(qlp + row * HDIM + seg);
        }
    }
    __syncthreads();

    uint32_t qfh[4][4], qfl[4][4];
    {
        const int lrow = lane & 15;
        const int lcol = (lane >> 4) * 8;
#pragma unroll
        for (int kk = 0; kk < 4; kk++) {
            uint32_t off = (uint32_t)((wid * 16 + lrow) * ATT_STRB + (kk * 16 + lcol) * 2);
            ldsm_x4(qfh[kk], smem_base + off);
            ldsm_x4(qfl[kk], smem_base + 9216 + off);
        }
    }
    __syncthreads();

    int nt;
    int kbs[5];
    bool is_band = false;
    if (heavy) {
        nt = 8;
    } else if (qb == NGB) {
        nt = 5; kbs[0]=0; kbs[1]=1; kbs[2]=2; kbs[3]=3; kbs[4]=4;
    } else if (qb == NB - 1) {
        nt = 5; kbs[0]=0; kbs[1]=1; kbs[2]=61; kbs[3]=62; kbs[4]=63;
    } else {
        nt = 5; kbs[0]=0; kbs[1]=1; kbs[2]=qb-1; kbs[3]=qb; kbs[4]=qb+1; is_band = true;
    }

#define KB_OF(IT) (heavy ? (ch * 8 + (IT)) : kbs[(IT)])

#define ISSUE_K(KB, STG) do {                                               \
    const __nv_bfloat16* khp_ = g_kh + bh64 + (size_t)(KB) * BLKSZ * HDIM;  \
    const __nv_bfloat16* klp_ = g_kl + bh64 + (size_t)(KB) * BLKSZ * HDIM;  \
    for (int i = t; i < 512; i += 128) {                                    \
        int row = i >> 3, seg = (i & 7) * 8;                                \
        uint32_t so = smem_base + KSTAGE(STG) + row * ATT_STRB + seg * 2;   \
        cp_async16(so,        khp_ + row * HDIM + seg);                     \
        cp_async16(so + 9216, klp_ + row * HDIM + seg);                     \
    }                                                                       \
    CP_COMMIT; } while (0)

#define ISSUE_VP(IT, KB, BANDT) do {                                        \
    const __nv_bfloat16* vhp_ = g_vh + bh64 + (size_t)(KB) * BLKSZ * HDIM;  \
    const __nv_bfloat16* vlp_ = g_vl + bh64 + (size_t)(KB) * BLKSZ * HDIM;  \
    for (int i = t; i < 512; i += 128) {                                    \
        int row = i >> 3, seg = (i & 7) * 8;                                \
        uint32_t so = smem_base + T_VH + row * ATT_STRB + seg * 2;          \
        cp_async16(so,        vhp_ + row * HDIM + seg);                     \
        cp_async16(so + 9216, vlp_ + row * HDIM + seg);                     \
    }                                                                       \
    if (BANDT) {                                                            \
        const float* bmb_ = band_mask                                       \
            + ((size_t)(b * 60 + (qb - 3)) * 64) * 192 + (size_t)((IT) - 2) * 64; \
        for (int i = t; i < 1024; i += 128) {                               \
            int row = i >> 4, c = i & 15;                                   \
            cp_async16(smem_base + T_PEN2 + row * 272 + c * 16,             \
                       bmb_ + row * 192 + c * 4);                           \
        }                                                                   \
    } else if (t < 16) {                                                    \
        cp_async16(smem_base + T_PEN1 + t * 16,                             \
                   to_mask + (size_t)b * SS + (KB) * BLKSZ + t * 4);        \
    }                                                                       \
    CP_COMMIT; } while (0)

    float m0 = -1e30f, m1 = -1e30f, l0 = 0.f, l1 = 0.f;
    float o[8][4];
#pragma unroll
    for (int nj = 0; nj < 8; nj++)
#pragma unroll
        for (int e = 0; e < 4; e++) o[nj][e] = 0.f;

    ISSUE_K(KB_OF(0), 0);

    for (int it = 0; it < nt; it++) {
        const int kb = KB_OF(it);
        const bool band_tile = (is_band && it >= 2);

        ISSUE_VP(it, kb, band_tile);
        if (it + 1 < nt) {
            ISSUE_K(KB_OF(it + 1), (it + 1) & 1);
            CP_WAIT2;
        } else {
            CP_WAIT1;
        }
        __syncthreads();

        const uint32_t kst = smem_base + KSTAGE(it & 1);
        float acc[8][4];
#pragma unroll
        for (int nj = 0; nj < 8; nj++)
#pragma unroll
            for (int e = 0; e < 4; e++) acc[nj][e] = 0.f;

#pragma unroll
        for (int nj = 0; nj < 8; nj++) {
            uint32_t kh8[8], kl8[8];
            uint32_t rbase = (uint32_t)((nj * 8 + (lane & 7)) * ATT_STRB + (lane >> 3) * 16);
            ldsm_x4(kh8,     kst + rbase);
            ldsm_x4(kh8 + 4, kst + rbase + 64);
            ldsm_x4(kl8,     kst + 9216 + rbase);
            ldsm_x4(kl8 + 4, kst + 9216 + rbase + 64);
#pragma unroll
            for (int kk = 0; kk < 4; kk++) {
                mma_bf16(acc[nj], qfh[kk], kh8[2*kk], kh8[2*kk+1]);
                mma_bf16(acc[nj], qfh[kk], kl8[2*kk], kl8[2*kk+1]);
                mma_bf16(acc[nj], qfl[kk], kh8[2*kk], kh8[2*kk+1]);
            }
        }

        if (it + 1 < nt) { CP_WAIT1; } else { CP_WAIT0; }
        __syncthreads();

        const int qr0 = wid * 16 + (lane >> 2);
#pragma unroll
        for (int nj = 0; nj < 8; nj++) {
#pragma unroll
            for (int e = 0; e < 4; e++) {
                int col = nj * 8 + (lane & 3) * 2 + (e & 1);
                float mv = band_tile
                    ? pen2f[(qr0 + (e >> 1) * 8) * 68 + col]
                    : pen1f[col];
                acc[nj][e] = acc[nj][e] * rs + (1.f - mv) * pen;
            }
        }

        float tm0 = -1e30f, tm1 = -1e30f;
#pragma unroll
        for (int nj = 0; nj < 8; nj++) {
            tm0 = fmaxf(tm0, fmaxf(acc[nj][0], acc[nj][1]));
            tm1 = fmaxf(tm1, fmaxf(acc[nj][2], acc[nj][3]));
        }
        tm0 = fmaxf(tm0, __shfl_xor_sync(0xffffffffu, tm0, 1));
        tm0 = fmaxf(tm0, __shfl_xor_sync(0xffffffffu, tm0, 2));
        tm1 = fmaxf(tm1, __shfl_xor_sync(0xffffffffu, tm1, 1));
        tm1 = fmaxf(tm1, __shfl_xor_sync(0xffffffffu, tm1, 2));

        float nm0 = fmaxf(m0, tm0), nm1 = fmaxf(m1, tm1);
        float c0 = __expf(m0 - nm0), c1 = __expf(m1 - nm1);
        float ts0 = 0.f, ts1 = 0.f;
#pragma unroll
        for (int nj = 0; nj < 8; nj++) {
            acc[nj][0] = __expf(acc[nj][0] - nm0);
            acc[nj][1] = __expf(acc[nj][1] - nm0);
            acc[nj][2] = __expf(acc[nj][2] - nm1);
            acc[nj][3] = __expf(acc[nj][3] - nm1);
            ts0 += acc[nj][0] + acc[nj][1];
            ts1 += acc[nj][2] + acc[nj][3];
        }
        ts0 += __shfl_xor_sync(0xffffffffu, ts0, 1);
        ts0 += __shfl_xor_sync(0xffffffffu, ts0, 2);
        ts1 += __shfl_xor_sync(0xffffffffu, ts1, 1);
        ts1 += __shfl_xor_sync(0xffffffffu, ts1, 2);
        l0 = l0 * c0 + ts0;  l1 = l1 * c1 + ts1;
        m0 = nm0;  m1 = nm1;
#pragma unroll
        for (int nj = 0; nj < 8; nj++) {
            o[nj][0] *= c0; o[nj][1] *= c0;
            o[nj][2] *= c1; o[nj][3] *= c1;
        }

        uint32_t phi[4][4], plo[4][4];
#pragma unroll
        for (int kk2 = 0; kk2 < 4; kk2++) {
            phi[kk2][0] = pack_hilo(acc[2*kk2][0],   acc[2*kk2][1],   plo[kk2][0]);
            phi[kk2][1] = pack_hilo(acc[2*kk2][2],   acc[2*kk2][3],   plo[kk2][1]);
            phi[kk2][2] = pack_hilo(acc[2*kk2+1][0], acc[2*kk2+1][1], plo[kk2][2]);
            phi[kk2][3] = pack_hilo(acc[2*kk2+1][2], acc[2*kk2+1][3], plo[kk2][3]);
        }

#pragma unroll
        for (int njd = 0; njd < 8; njd++) {
#pragma unroll
            for (int kk2 = 0; kk2 < 4; kk2++) {
                uint32_t vh[2], vl[2];
                uint32_t off = (uint32_t)((kk2 * 16 + (lane & 15)) * ATT_STRB + njd * 16);
                ldsm_x2_trans(vh, smem_base + T_VH + off);
                ldsm_x2_trans(vl, smem_base + T_VL + off);
                mma_bf16(o[njd], phi[kk2], vh[0], vh[1]);
                mma_bf16(o[njd], phi[kk2], vl[0], vl[1]);
                mma_bf16(o[njd], plo[kk2], vh[0], vh[1]);
            }
        }
        __syncthreads();
    }

    const int r0 = wid * 16 + (lane >> 2);
    if (!heavy) {
        const int s0 = qb * BLKSZ + r0;
        const int s1 = s0 + 8;
        float inv0 = from_mask[(size_t)b * SS + s0] / l0;
        float inv1 = from_mask[(size_t)b * SS + s1] / l1;
#pragma unroll
        for (int njd = 0; njd < 8; njd++) {
            const int col = njd * 8 + (lane & 3) * 2;
            {
                size_t idx = ((size_t)b * SS + s0) * DD + h * HDIM + col;
                uint32_t lo, hi = pack_hilo(o[njd][0] * inv0, o[njd][1] * inv0, lo);
                *(uint32_t*)(g_c_hi + idx) = hi;
                *(uint32_t*)(g_c_lo + idx) = lo;
            }
            {
                size_t idx = ((size_t)b * SS + s1) * DD + h * HDIM + col;
                uint32_t lo, hi = pack_hilo(o[njd][2] * inv1, o[njd][3] * inv1, lo);
                *(uint32_t*)(g_c_hi + idx) = hi;
                *(uint32_t*)(g_c_lo + idx) = lo;
            }
        }
    } else {
        const int cid = ((b * HH + h) * 2 + qb) * 8 + ch;
        float* pob = g_po + (size_t)cid * 4096;
#pragma unroll
        for (int njd = 0; njd < 8; njd++) {
            const int col = njd * 8 + (lane & 3) * 2;
            float2 s0v; s0v.x = o[njd][0]; s0v.y = o[njd][1];
            float2 s1v; s1v.x = o[njd][2]; s1v.y = o[njd][3];
            *(float2*)(pob + r0 * 64 + col) = s0v;
            *(float2*)(pob + (r0 + 8) * 64 + col) = s1v;
        }
        if ((lane & 3) == 0) {
            g_pm[cid * 64 + r0]     = m0;
            g_pm[cid * 64 + r0 + 8] = m1;
            g_pl[cid * 64 + r0]     = l0;
            g_pl[cid * 64 + r0 + 8] = l1;
        }
    }
}

// ---------------------------------------------------------------------------
// Combine split-KV partials, 8x parallelized: grid 512, block 128.
// bx>>3 = (b,h,qb) id; bx&7 = row-subgroup. Thread: r = sub*8 + (t>>4),
// cols = (t&15)*4 .. +3.
// ---------------------------------------------------------------------------
__global__ __launch_bounds__(128) void attn_combine(const float* __restrict__ from_mask)
{
    const int bx  = blockIdx.x;
    const int x   = bx >> 3;
    const int sub = bx & 7;
    const int qb = x & 1;
    const int h  = (x >> 1) & 15;
    const int b  = x >> 5;
    const int t  = threadIdx.x;
    const int r  = sub * 8 + (t >> 4);
    const int c0 = (t & 15) * 4;
    const int base8 = x * 8;

    float m[8], l[8], M = -1e30f;
#pragma unroll
    for (int i = 0; i < 8; i++) {
        m[i] = g_pm[(base8 + i) * 64 + r];
        l[i] = g_pl[(base8 + i) * 64 + r];
        M = fmaxf(M, m[i]);
    }
    float L = 0.f, sc[8];
#pragma unroll
    for (int i = 0; i < 8; i++) { sc[i] = __expf(m[i] - M); L += l[i] * sc[i]; }

    float acc[4];
#pragma unroll
    for (int c = 0; c < 4; c++) acc[c] = 0.f;
#pragma unroll
    for (int i = 0; i < 8; i++) {
        float4 v = *(const float4*)(g_po + (size_t)(base8 + i) * 4096 + r * 64 + c0);
        float s = sc[i];
        acc[0] += s * v.x; acc[1] += s * v.y; acc[2] += s * v.z; acc[3] += s * v.w;
    }

    const int s_ = qb * BLKSZ + r;
    float inv = from_mask[(size_t)b * SS + s_] / L;
    size_t idx = ((size_t)b * SS + s_) * DD + h * HDIM + c0;
    uint32_t lo0, hi0 = pack_hilo(acc[0] * inv, acc[1] * inv, lo0);
    uint32_t lo1, hi1 = pack_hilo(acc[2] * inv, acc[3] * inv, lo1);
    *(uint32_t*)(g_c_hi + idx)     = hi0;
    *(uint32_t*)(g_c_hi + idx + 2) = hi1;
    *(uint32_t*)(g_c_lo + idx)     = lo0;
    *(uint32_t*)(g_c_lo + idx + 2) = lo1;
}

// ---------------------------------------------------------------------------
extern "C" void kernel_launch(void* const* d_in, const int* in_sizes, int n_in,
                              void* d_out, int out_size)
{
    const float* tokens    = (const float*)d_in[0];
    const float* band_mask = (const float*)d_in[1];
    const float* from_mask = (const float*)d_in[2];
    const float* to_mask   = (const float*)d_in[3];
    const float* Wq        = (const float*)d_in[4];
    const float* Wk        = (const float*)d_in[5];
    const float* Wv        = (const float*)d_in[6];
    const float* Wu        = (const float*)d_in[7];
    const float* bu        = (const float*)d_in[8];
    float* out = (float*)d_out;

    cudaFuncSetAttribute(attn_kernel,
                         cudaFuncAttributeMaxDynamicSharedMemorySize, ATTN_SMEM_BYTES);
    cudaFuncSetAttribute(gemm_hmma_kernel,
                         cudaFuncAttributeMaxDynamicSharedMemorySize, GEMM_SMEM_BYTES);

    // 0) Fused precision-split of tokens + all four weights
    prep_split_kernel<<<12288, 256>>>(tokens, Wq, Wk, Wv, Wu);

    // 1) QKV projections (3-stage pipelined HMMA, const-buffer unrolled)
    gemm_hmma_kernel<<<dim3(8, 64, 3), 256, GEMM_SMEM_BYTES>>>(0, nullptr, nullptr);

    // 2) Sparse attention (heavy CTAs first in grid order)
    attn_kernel<<<dim3(78, HH, BB), 128, ATTN_SMEM_BYTES>>>(band_mask, from_mask, to_mask);

    // 2b) Combine heavy partials (8x parallelized)
    attn_combine<<<512, 128>>>(from_mask);

    // 3) Output projection + bias (3-stage pipelined HMMA)
    gemm_hmma_kernel<<<dim3(8, 64, 1), 256, GEMM_SMEM_BYTES>>>(3, bu, out);
}